// round 7
// baseline (speedup 1.0000x reference)
#include <cuda_runtime.h>
#include <cuda_bf16.h>
#include <math.h>
#include <stdint.h>

#define BN_EPS 1e-3f
#define SLOPE  0.1f
#define CT     30.0f

// ============================ scratch globals ============================
__device__ float g_h1[256 * 128 * 1024];
__device__ float g_h2[256 * 256 * 256];
__device__ float g_data[256 * 4096];
__device__ float g_muA[16 * 4096];
__device__ float g_muB[16 * 4096];
__device__ float g_r[256 * 16];
__device__ __nv_bfloat16 g_A1[256 * 1024 * 128];
__device__ __nv_bfloat16 g_A2[65536ull * 2304];
__device__ __nv_bfloat16 g_A3[16384ull * 4608];
__device__ __nv_bfloat16 g_B1[128 * 128];
__device__ __nv_bfloat16 g_B2[256 * 2304];
__device__ __nv_bfloat16 g_B3[64 * 4608];

__device__ __forceinline__ void bf16_split(float x, unsigned short& h, unsigned short& l) {
    __nv_bfloat16 hb = __float2bfloat16(x);
    h = __bfloat16_as_ushort(hb);
    l = __bfloat16_as_ushort(__float2bfloat16(x - __bfloat162float(hb)));
}
__device__ __forceinline__ uint32_t smem_u32(const void* p) {
    uint32_t a;
    asm("{ .reg .u64 t; cvta.to.shared.u64 t, %1; cvt.u32.u64 %0, t; }" : "=r"(a) : "l"(p));
    return a;
}
__device__ __forceinline__ void cp_async16(uint32_t dst, const void* src) {
    asm volatile("cp.async.cg.shared.global [%0], [%1], 16;" :: "r"(dst), "l"(src));
}
__device__ __forceinline__ void ldsm_x4(uint32_t* f, uint32_t addr) {
    asm volatile("ldmatrix.sync.aligned.m8n8.x4.shared.b16 {%0,%1,%2,%3}, [%4];"
                 : "=r"(f[0]), "=r"(f[1]), "=r"(f[2]), "=r"(f[3]) : "r"(addr));
}
__device__ __forceinline__ void mma_bf16(float* d, const uint32_t* a, const uint32_t* b) {
    asm volatile(
        "mma.sync.aligned.m16n8k16.row.col.f32.bf16.bf16.f32 "
        "{%0,%1,%2,%3}, {%4,%5,%6,%7}, {%8,%9}, {%0,%1,%2,%3};"
        : "+f"(d[0]), "+f"(d[1]), "+f"(d[2]), "+f"(d[3])
        : "r"(a[0]), "r"(a[1]), "r"(a[2]), "r"(a[3]), "r"(b[0]), "r"(b[1]));
}

// ============================ weight prep ============================
__global__ __launch_bounds__(128) void prep_w1(const float* __restrict__ w, __nv_bfloat16* __restrict__ o)
{
    int oc = threadIdx.x;
    unsigned short h[27], l[27];
#pragma unroll
    for (int j = 0; j < 27; j++) bf16_split(w[oc * 27 + j], h[j], l[j]);
    __nv_bfloat16* row = o + oc * 128;
#pragma unroll
    for (int j = 0; j < 27; j++) {
        row[j]      = __ushort_as_bfloat16(h[j]);
        row[27 + j] = __ushort_as_bfloat16(l[j]);
        row[54 + j] = __ushort_as_bfloat16(h[j]);
    }
#pragma unroll
    for (int j = 81; j < 128; j++) row[j] = __ushort_as_bfloat16(0);
}
__global__ __launch_bounds__(256) void prep_w2(const float* __restrict__ w, __nv_bfloat16* __restrict__ o)
{
    int oc = blockIdx.x;
    for (int k = threadIdx.x; k < 1152; k += 256) {
        unsigned short h, l; bf16_split(w[oc * 1152 + k], h, l);
        o[oc * 2304 + k] = __ushort_as_bfloat16(h);
        o[oc * 2304 + 1152 + k] = __ushort_as_bfloat16(l);
    }
}
__global__ __launch_bounds__(256) void prep_w3(const float* __restrict__ w, __nv_bfloat16* __restrict__ o)
{
    int oc = blockIdx.x;
    for (int k = threadIdx.x; k < 2304; k += 256) {
        unsigned short h, l; bf16_split(w[oc * 2304 + k], h, l);
        o[oc * 4608 + k] = __ushort_as_bfloat16(h);
        o[oc * 4608 + 2304 + k] = __ushort_as_bfloat16(l);
    }
}

// ============================ im2col ============================
// grid(256, 4): y = output quadrant (256 positions each)
__global__ __launch_bounds__(256) void im2col1(const float* __restrict__ x, __nv_bfloat16* __restrict__ A)
{
    __shared__ float s[12288];
    int img = blockIdx.x, tid = threadIdx.x;
    const float* xin = x + img * 12288;
    for (int i = tid; i < 12288; i += 256) s[i] = xin[i];
    __syncthreads();
    int p = tid + blockIdx.y * 256;
    int oh = p >> 5, ow = p & 31;
    uint32_t t[64];
#pragma unroll
    for (int i = 0; i < 64; i++) t[i] = 0;
#pragma unroll
    for (int j = 0; j < 27; j++) {
        int ic = j / 9, kk = j % 9, kh = kk / 3, kw = kk % 3;
        int ih = 2 * oh - 1 + kh, iw = 2 * ow - 1 + kw;
        float val = (ih >= 0 && ih < 64 && iw >= 0 && iw < 64) ? s[ic * 4096 + ih * 64 + iw] : 0.f;
        unsigned short h, l; bf16_split(val, h, l);
        t[j >> 1]        |= (uint32_t)h << ((j & 1) * 16);
        t[(j + 27) >> 1] |= (uint32_t)h << (((j + 27) & 1) * 16);
        t[(j + 54) >> 1] |= (uint32_t)l << (((j + 54) & 1) * 16);
    }
    uint4* row = (uint4*)(A + ((size_t)(img * 1024 + p)) * 128);
#pragma unroll
    for (int w = 0; w < 16; w++) row[w] = make_uint4(t[4*w], t[4*w+1], t[4*w+2], t[4*w+3]);
}

// grid(256, 4): y handles 4 of the 16 ic-chunks
__global__ __launch_bounds__(256) void im2col2(const float* __restrict__ in, __nv_bfloat16* __restrict__ A)
{
    __shared__ float s[8192];
    int img = blockIdx.x, tid = threadIdx.x;
    int p = tid, oh = p >> 4, ow = p & 15;
    char* rowb = (char*)(A + ((size_t)(img * 256 + p)) * 2304);
    for (int ii = 0; ii < 4; ii++) {
        int icb = blockIdx.y * 4 + ii;
        __syncthreads();
        const float* ip = in + ((size_t)img * 128 + icb * 8) * 1024;
        for (int i = tid; i < 8192; i += 256) s[i] = ip[i];
        __syncthreads();
        uint32_t th[36], tl[36];
#pragma unroll
        for (int u = 0; u < 36; u++) {
            uint32_t hv = 0, lv = 0;
#pragma unroll
            for (int half = 0; half < 2; half++) {
                int j = 2 * u + half;
                int ic8 = j / 9, kk = j % 9, kh = kk / 3, kw = kk % 3;
                int ih = 2 * oh - 1 + kh, iw = 2 * ow - 1 + kw;
                float val = (ih >= 0 && ih < 32 && iw >= 0 && iw < 32) ? s[ic8 * 1024 + (ih << 5) + iw] : 0.f;
                unsigned short h, l; bf16_split(val, h, l);
                hv |= (uint32_t)h << (half * 16);
                lv |= (uint32_t)l << (half * 16);
            }
            th[u] = hv; tl[u] = lv;
        }
        uint4* oh4 = (uint4*)(rowb + icb * 144);
        uint4* ol4 = (uint4*)(rowb + 2304 + icb * 144);
#pragma unroll
        for (int w = 0; w < 9; w++) {
            oh4[w] = make_uint4(th[4*w], th[4*w+1], th[4*w+2], th[4*w+3]);
            ol4[w] = make_uint4(tl[4*w], tl[4*w+1], tl[4*w+2], tl[4*w+3]);
        }
    }
}

// grid(256, 2): y handles 4 of the 8 ic-chunks
__global__ __launch_bounds__(256) void im2col3(const float* __restrict__ in, __nv_bfloat16* __restrict__ A)
{
    __shared__ float s[8192];
    int img = blockIdx.x, tid = threadIdx.x;
    int p = tid & 63, q = tid >> 6;
    int oh = p >> 3, ow = p & 7;
    char* rowb = (char*)(A + ((size_t)(img * 64 + p)) * 4608);
    for (int ii = 0; ii < 4; ii++) {
        int icb = blockIdx.y * 4 + ii;
        __syncthreads();
        const float* ip = in + ((size_t)img * 256 + icb * 32) * 256;
        for (int i = tid; i < 8192; i += 256) s[i] = ip[i];
        __syncthreads();
        uint32_t th[36], tl[36];
#pragma unroll
        for (int u = 0; u < 36; u++) {
            uint32_t hv = 0, lv = 0;
#pragma unroll
            for (int half = 0; half < 2; half++) {
                int j = 2 * u + half;
                int ic8 = j / 9, kk = j % 9, kh = kk / 3, kw = kk % 3;
                int ih = 2 * oh - 1 + kh, iw = 2 * ow - 1 + kw;
                float val = (ih >= 0 && ih < 16 && iw >= 0 && iw < 16)
                                ? s[(q * 8 + ic8) * 256 + (ih << 4) + iw] : 0.f;
                unsigned short h, l; bf16_split(val, h, l);
                hv |= (uint32_t)h << (half * 16);
                lv |= (uint32_t)l << (half * 16);
            }
            th[u] = hv; tl[u] = lv;
        }
        uint4* oh4 = (uint4*)(rowb + icb * 576 + q * 144);
        uint4* ol4 = (uint4*)(rowb + 4608 + icb * 576 + q * 144);
#pragma unroll
        for (int w = 0; w < 9; w++) {
            oh4[w] = make_uint4(th[4*w], th[4*w+1], th[4*w+2], th[4*w+3]);
            ol4[w] = make_uint4(tl[4*w], tl[4*w+1], tl[4*w+2], tl[4*w+3]);
        }
    }
}

// ============================ HMMA GEMM (mma.sync bf16) ============================
template<int CONV>
__global__ __launch_bounds__(256)
void gemm_kernel(const __nv_bfloat16* __restrict__ A, const __nv_bfloat16* __restrict__ Bw,
                 const float* __restrict__ bias, const float* __restrict__ g,
                 const float* __restrict__ beta, const float* __restrict__ m,
                 const float* __restrict__ v, float* __restrict__ out)
{
    constexpr int N  = (CONV == 2) ? 256 : ((CONV == 1) ? 128 : 64);
    constexpr int NC = (CONV == 1) ? 2 : ((CONV == 2) ? 54 : 108);
    constexpr int KS = (CONV == 1) ? 128 : ((CONV == 2) ? 2304 : 4608);
    constexpr int HC = (CONV == 1) ? 2 : ((CONV == 2) ? 18 : 36);
    constexpr int BN = (N > 128) ? 128 : N;
    constexpr int WN = BN / 2;
    constexpr int NT = WN / 8;
    constexpr int ABUF = 128 * 144;
    constexpr int BBUF = BN * 144;
    constexpr int BGI = (BN * 8) / 256;
    constexpr int P = BN + 1;

    extern __shared__ __align__(16) char smem[];
    __shared__ float scs[256], shs[256];

    int tid = threadIdx.x, wid = tid >> 5, lane = tid & 31;
    int wm = wid & 3, wn = wid >> 2;
    int rowbase = blockIdx.x * 128;
    int nb0 = blockIdx.y * BN;

    if (tid < N) {
        float sc = g[tid] / sqrtf(v[tid] + BN_EPS);
        scs[tid] = sc;
        shs[tid] = beta[tid] - m[tid] * sc + bias[tid] * sc;
    }

    uint32_t sb = smem_u32(smem);

    float acc[2][NT][4];
#pragma unroll
    for (int i = 0; i < 2; i++)
#pragma unroll
        for (int j = 0; j < NT; j++)
#pragma unroll
            for (int q = 0; q < 4; q++) acc[i][j][q] = 0.f;

    auto issue_copy = [&](int c) {
        int Ai = (c < HC) ? c : c - HC;
        int Bi = (c < 2 * HC) ? c : c - 2 * HC;
        int buf = c & 1;
        uint32_t ab = sb + buf * (ABUF + BBUF);
        uint32_t bb = ab + ABUF;
#pragma unroll
        for (int i = 0; i < 4; i++) {
            int gi = tid + 256 * i; int rr = gi >> 3, gc = gi & 7;
            cp_async16(ab + rr * 144 + gc * 16,
                       (const char*)A + ((size_t)(rowbase + rr) * KS + Ai * 64) * 2 + gc * 16);
        }
#pragma unroll
        for (int i = 0; i < BGI; i++) {
            int gi = tid + 256 * i; int rr = gi >> 3, gc = gi & 7;
            cp_async16(bb + rr * 144 + gc * 16,
                       (const char*)Bw + ((size_t)(nb0 + rr) * KS + Bi * 64) * 2 + gc * 16);
        }
        asm volatile("cp.async.commit_group;");
    };

    issue_copy(0);
    for (int c = 0; c < NC; c++) {
        if (c + 1 < NC) {
            issue_copy(c + 1);
            asm volatile("cp.async.wait_group 1;");
        } else {
            asm volatile("cp.async.wait_group 0;");
        }
        __syncthreads();

        int buf = c & 1;
        uint32_t ab = sb + buf * (ABUF + BBUF);
        uint32_t bb = ab + ABUF;
#pragma unroll
        for (int ks = 0; ks < 4; ks++) {
            uint32_t af[2][4];
#pragma unroll
            for (int mt = 0; mt < 2; mt++) {
                uint32_t addr = ab + (wm * 32 + mt * 16 + (lane & 15)) * 144
                                + ks * 32 + ((lane >> 4) << 4);
                ldsm_x4(af[mt], addr);
            }
#pragma unroll
            for (int nt2 = 0; nt2 < NT / 2; nt2++) {
                uint32_t bf[4];
                uint32_t addr = bb + (wn * WN + nt2 * 16 + (lane & 7) + (((lane >> 4) & 1) << 3)) * 144
                                + ks * 32 + (((lane >> 3) & 1) << 4);
                ldsm_x4(bf, addr);
#pragma unroll
                for (int mt = 0; mt < 2; mt++) {
                    mma_bf16(acc[mt][2 * nt2],     af[mt], bf);
                    mma_bf16(acc[mt][2 * nt2 + 1], af[mt], bf + 2);
                }
            }
        }
        __syncthreads();
    }

    float* stage = (float*)smem;
#pragma unroll
    for (int mt = 0; mt < 2; mt++)
#pragma unroll
        for (int nt = 0; nt < NT; nt++) {
            int r0 = wm * 32 + mt * 16 + (lane >> 2);
            int c0 = wn * WN + nt * 8 + 2 * (lane & 3);
            stage[r0 * P + c0]           = acc[mt][nt][0];
            stage[r0 * P + c0 + 1]       = acc[mt][nt][1];
            stage[(r0 + 8) * P + c0]     = acc[mt][nt][2];
            stage[(r0 + 8) * P + c0 + 1] = acc[mt][nt][3];
        }
    __syncthreads();

#pragma unroll
    for (int j = 0; j < BN / 8; j++) {
        int colL = wid * (BN / 8) + j;
        int gcol = nb0 + colL;
        float sc = scs[gcol], sh = shs[gcol];
#pragma unroll
        for (int it = 0; it < 4; it++) {
            int r = it * 32 + lane;
            float y = stage[r * P + colL] * sc + sh;
            y = y > 0.f ? y : SLOPE * y;
            int grow = rowbase + r;
            if (CONV == 1) {
                int img = grow >> 10, p = grow & 1023;
                out[((size_t)(img * 128 + gcol)) * 1024 + p] = y;
            } else if (CONV == 2) {
                int img = grow >> 8, p = grow & 255;
                out[((size_t)(img * 256 + gcol)) * 256 + p] = y;
            } else {
                int img = grow >> 6, p = grow & 63;
                out[(size_t)img * 4096 + gcol * 64 + p] = y;
            }
        }
    }
}

// ============================ k-means ============================
__global__ __launch_bounds__(256) void normalize_kernel(float* __restrict__ data)
{
    int row = blockIdx.x, tid = threadIdx.x;
    float* dr = data + row * 4096;
    float vals[16];
    float s = 0.f;
#pragma unroll
    for (int i = 0; i < 16; i++) { vals[i] = dr[tid + i * 256]; s = fmaf(vals[i], vals[i], s); }
    __shared__ float sm[9];
    int lane = tid & 31, warp = tid >> 5;
#pragma unroll
    for (int off = 16; off > 0; off >>= 1) s += __shfl_down_sync(0xffffffffu, s, off);
    if (lane == 0) sm[warp] = s;
    __syncthreads();
    if (tid == 0) {
        float t = 0.f;
        for (int w = 0; w < 8; w++) t += sm[w];
        sm[8] = 1.f / sqrtf(t);
    }
    __syncthreads();
    float inv = sm[8];
#pragma unroll
    for (int i = 0; i < 16; i++) dr[tid + i * 256] = vals[i] * inv;
}

__global__ __launch_bounds__(256) void copy_kernel(const float* __restrict__ src, float* __restrict__ dst)
{
    int i = blockIdx.x * 256 + threadIdx.x;
    if (i < 16 * 4096) dst[i] = src[i];
}

__global__ __launch_bounds__(256) void dist_softmax_kernel(
    const float* __restrict__ data, const float* __restrict__ mu, float* __restrict__ rout)
{
    int row = blockIdx.x, tid = threadIdx.x;
    const float* dr = data + row * 4096;
    float acc[16];
#pragma unroll
    for (int k = 0; k < 16; k++) acc[k] = 0.f;
#pragma unroll 4
    for (int i = 0; i < 16; i++) {
        int j = tid + i * 256;
        float dj = __ldg(dr + j);
#pragma unroll
        for (int k = 0; k < 16; k++) acc[k] = fmaf(dj, __ldg(mu + k * 4096 + j), acc[k]);
    }
    __shared__ float wsum[8][16];
    int lane = tid & 31, warp = tid >> 5;
#pragma unroll
    for (int k = 0; k < 16; k++) {
        float vv = acc[k];
#pragma unroll
        for (int off = 16; off > 0; off >>= 1) vv += __shfl_down_sync(0xffffffffu, vv, off);
        if (lane == 0) wsum[warp][k] = vv;
    }
    __syncthreads();
    if (tid == 0) {
        float d[16];
        float mx = -1e30f;
#pragma unroll
        for (int k = 0; k < 16; k++) {
            float s = 0.f;
            for (int w = 0; w < 8; w++) s += wsum[w][k];
            d[k] = CT * s;
            mx = fmaxf(mx, d[k]);
        }
        float sum = 0.f;
#pragma unroll
        for (int k = 0; k < 16; k++) { d[k] = expf(d[k] - mx); sum += d[k]; }
        float inv = 1.f / sum;
#pragma unroll
        for (int k = 0; k < 16; k++) rout[row * 16 + k] = d[k] * inv;
    }
}

// grid(128), block(256): 32 features x 8 n-slices per block, smem reduce
__global__ __launch_bounds__(256) void update_mu_kernel(
    const float* __restrict__ r, const float* __restrict__ data, float* __restrict__ mu_out)
{
    __shared__ float rs[256 * 16];     // 16 KB
    __shared__ float red[8][512];      // 16 KB
    __shared__ float inv_cs[16];
    int tid = threadIdx.x;
    int fl = tid & 31, ng = tid >> 5;
    int f = blockIdx.x * 32 + fl;

    for (int i = tid; i < 4096; i += 256) rs[i] = r[i];
    __syncthreads();
    if (tid < 16) {
        float s = 0.f;
#pragma unroll 8
        for (int n = 0; n < 256; n++) s += rs[n * 16 + tid];
        inv_cs[tid] = 1.f / s;
    }

    float acc[16];
#pragma unroll
    for (int k = 0; k < 16; k++) acc[k] = 0.f;
    int n0 = ng * 32;
#pragma unroll 4
    for (int n = n0; n < n0 + 32; n++) {
        float d = __ldg(data + (size_t)n * 4096 + f);
#pragma unroll
        for (int k = 0; k < 16; k++) acc[k] = fmaf(rs[n * 16 + k], d, acc[k]);
    }
    float4* rp = (float4*)&red[ng][fl * 16];
    rp[0] = make_float4(acc[0], acc[1], acc[2], acc[3]);
    rp[1] = make_float4(acc[4], acc[5], acc[6], acc[7]);
    rp[2] = make_float4(acc[8], acc[9], acc[10], acc[11]);
    rp[3] = make_float4(acc[12], acc[13], acc[14], acc[15]);
    __syncthreads();

#pragma unroll
    for (int rep = 0; rep < 2; rep++) {
        int idx = tid + rep * 256;           // idx = fl2*16 + k
        float s = 0.f;
#pragma unroll
        for (int gg = 0; gg < 8; gg++) s += red[gg][idx];
        int fl2 = idx >> 4, k = idx & 15;
        mu_out[(size_t)k * 4096 + blockIdx.x * 32 + fl2] = s * inv_cs[k];
    }
}

// ============================ host ============================
extern "C" void kernel_launch(void* const* d_in, const int* in_sizes, int n_in,
                              void* d_out, int out_size)
{
    const float* x   = (const float*)d_in[0];
    const float* w1  = (const float*)d_in[1];
    const float* b1  = (const float*)d_in[2];
    const float* g1  = (const float*)d_in[3];
    const float* be1 = (const float*)d_in[4];
    const float* m1  = (const float*)d_in[5];
    const float* v1  = (const float*)d_in[6];
    const float* w2  = (const float*)d_in[7];
    const float* b2  = (const float*)d_in[8];
    const float* g2  = (const float*)d_in[9];
    const float* be2 = (const float*)d_in[10];
    const float* m2  = (const float*)d_in[11];
    const float* v2  = (const float*)d_in[12];
    const float* w3  = (const float*)d_in[13];
    const float* b3  = (const float*)d_in[14];
    const float* g3  = (const float*)d_in[15];
    const float* be3 = (const float*)d_in[16];
    const float* m3  = (const float*)d_in[17];
    const float* v3  = (const float*)d_in[18];
    const float* mu0 = (const float*)d_in[19];

    float *h1, *h2, *data, *muA, *muB, *r;
    __nv_bfloat16 *A1, *A2, *A3, *B1, *B2, *B3;
    cudaGetSymbolAddress((void**)&h1, g_h1);
    cudaGetSymbolAddress((void**)&h2, g_h2);
    cudaGetSymbolAddress((void**)&data, g_data);
    cudaGetSymbolAddress((void**)&muA, g_muA);
    cudaGetSymbolAddress((void**)&muB, g_muB);
    cudaGetSymbolAddress((void**)&r, g_r);
    cudaGetSymbolAddress((void**)&A1, g_A1);
    cudaGetSymbolAddress((void**)&A2, g_A2);
    cudaGetSymbolAddress((void**)&A3, g_A3);
    cudaGetSymbolAddress((void**)&B1, g_B1);
    cudaGetSymbolAddress((void**)&B2, g_B2);
    cudaGetSymbolAddress((void**)&B3, g_B3);

    const int smem12 = 2 * (128 * 144 + 128 * 144);
    const int smem3  = 2 * (128 * 144 + 64 * 144);
    cudaFuncSetAttribute(gemm_kernel<1>, cudaFuncAttributeMaxDynamicSharedMemorySize, smem12);
    cudaFuncSetAttribute(gemm_kernel<2>, cudaFuncAttributeMaxDynamicSharedMemorySize, smem12);
    cudaFuncSetAttribute(gemm_kernel<3>, cudaFuncAttributeMaxDynamicSharedMemorySize, smem3);

    prep_w1<<<1, 128>>>(w1, B1);
    prep_w2<<<256, 256>>>(w2, B2);
    prep_w3<<<64, 256>>>(w3, B3);

    im2col1<<<dim3(256, 4), 256>>>(x, A1);
    gemm_kernel<1><<<dim3(2048, 1), 256, smem12>>>(A1, B1, b1, g1, be1, m1, v1, h1);
    im2col2<<<dim3(256, 4), 256>>>(h1, A2);
    gemm_kernel<2><<<dim3(512, 2), 256, smem12>>>(A2, B2, b2, g2, be2, m2, v2, h2);
    im2col3<<<dim3(256, 2), 256>>>(h2, A3);
    gemm_kernel<3><<<dim3(128, 1), 256, smem3>>>(A3, B3, b3, g3, be3, m3, v3, data);

    normalize_kernel<<<256, 256>>>(data);
    copy_kernel<<<256, 256>>>(mu0, muA);
    for (int it = 0; it < 11; it++) {
        dist_softmax_kernel<<<256, 256>>>(data, muA, r);
        update_mu_kernel<<<128, 256>>>(r, data, muB);
        float* t = muA; muA = muB; muB = t;
    }
    dist_softmax_kernel<<<256, 256>>>(data, muA, (float*)d_out);
}

// round 8
// speedup vs baseline: 1.2208x; 1.2208x over previous
#include <cuda_runtime.h>
#include <cuda_bf16.h>
#include <math.h>
#include <stdint.h>

#define BN_EPS 1e-3f
#define SLOPE  0.1f
#define CT     30.0f

// ============================ scratch globals ============================
__device__ float g_h1[256 * 128 * 1024];
__device__ float g_h2[256 * 256 * 256];
__device__ float g_data[256 * 4096];
__device__ float g_G[256 * 256];
__device__ float g_D0[256 * 16];
__device__ __nv_bfloat16 g_A1[256 * 1024 * 128];
__device__ __nv_bfloat16 g_A2[65536ull * 2304];
__device__ __nv_bfloat16 g_A3[16384ull * 4608];
__device__ __nv_bfloat16 g_B1[128 * 128];
__device__ __nv_bfloat16 g_B2[256 * 2304];
__device__ __nv_bfloat16 g_B3[64 * 4608];

__device__ __forceinline__ void bf16_split(float x, unsigned short& h, unsigned short& l) {
    __nv_bfloat16 hb = __float2bfloat16(x);
    h = __bfloat16_as_ushort(hb);
    l = __bfloat16_as_ushort(__float2bfloat16(x - __bfloat162float(hb)));
}
__device__ __forceinline__ uint32_t smem_u32(const void* p) {
    uint32_t a;
    asm("{ .reg .u64 t; cvta.to.shared.u64 t, %1; cvt.u32.u64 %0, t; }" : "=r"(a) : "l"(p));
    return a;
}
__device__ __forceinline__ void cp_async16(uint32_t dst, const void* src) {
    asm volatile("cp.async.cg.shared.global [%0], [%1], 16;" :: "r"(dst), "l"(src));
}
__device__ __forceinline__ void ldsm_x4(uint32_t* f, uint32_t addr) {
    asm volatile("ldmatrix.sync.aligned.m8n8.x4.shared.b16 {%0,%1,%2,%3}, [%4];"
                 : "=r"(f[0]), "=r"(f[1]), "=r"(f[2]), "=r"(f[3]) : "r"(addr));
}
__device__ __forceinline__ void mma_bf16(float* d, const uint32_t* a, const uint32_t* b) {
    asm volatile(
        "mma.sync.aligned.m16n8k16.row.col.f32.bf16.bf16.f32 "
        "{%0,%1,%2,%3}, {%4,%5,%6,%7}, {%8,%9}, {%0,%1,%2,%3};"
        : "+f"(d[0]), "+f"(d[1]), "+f"(d[2]), "+f"(d[3])
        : "r"(a[0]), "r"(a[1]), "r"(a[2]), "r"(a[3]), "r"(b[0]), "r"(b[1]));
}

// ============================ weight prep ============================
__global__ __launch_bounds__(128) void prep_w1(const float* __restrict__ w, __nv_bfloat16* __restrict__ o)
{
    int oc = threadIdx.x;
    unsigned short h[27], l[27];
#pragma unroll
    for (int j = 0; j < 27; j++) bf16_split(w[oc * 27 + j], h[j], l[j]);
    __nv_bfloat16* row = o + oc * 128;
#pragma unroll
    for (int j = 0; j < 27; j++) {
        row[j]      = __ushort_as_bfloat16(h[j]);
        row[27 + j] = __ushort_as_bfloat16(l[j]);
        row[54 + j] = __ushort_as_bfloat16(h[j]);
    }
#pragma unroll
    for (int j = 81; j < 128; j++) row[j] = __ushort_as_bfloat16(0);
}
__global__ __launch_bounds__(256) void prep_w2(const float* __restrict__ w, __nv_bfloat16* __restrict__ o)
{
    int oc = blockIdx.x;
    for (int k = threadIdx.x; k < 1152; k += 256) {
        unsigned short h, l; bf16_split(w[oc * 1152 + k], h, l);
        o[oc * 2304 + k] = __ushort_as_bfloat16(h);
        o[oc * 2304 + 1152 + k] = __ushort_as_bfloat16(l);
    }
}
__global__ __launch_bounds__(256) void prep_w3(const float* __restrict__ w, __nv_bfloat16* __restrict__ o)
{
    int oc = blockIdx.x;
    for (int k = threadIdx.x; k < 2304; k += 256) {
        unsigned short h, l; bf16_split(w[oc * 2304 + k], h, l);
        o[oc * 4608 + k] = __ushort_as_bfloat16(h);
        o[oc * 4608 + 2304 + k] = __ushort_as_bfloat16(l);
    }
}

// ============================ im2col ============================
// R6 form: grid(256), each thread 4 positions
__global__ __launch_bounds__(256) void im2col1(const float* __restrict__ x, __nv_bfloat16* __restrict__ A)
{
    __shared__ float s[12288];
    int img = blockIdx.x, tid = threadIdx.x;
    const float* xin = x + img * 12288;
    for (int i = tid; i < 12288; i += 256) s[i] = xin[i];
    __syncthreads();
#pragma unroll
    for (int pp = 0; pp < 4; pp++) {
        int p = tid + pp * 256;
        int oh = p >> 5, ow = p & 31;
        uint32_t t[64];
#pragma unroll
        for (int i = 0; i < 64; i++) t[i] = 0;
#pragma unroll
        for (int j = 0; j < 27; j++) {
            int ic = j / 9, kk = j % 9, kh = kk / 3, kw = kk % 3;
            int ih = 2 * oh - 1 + kh, iw = 2 * ow - 1 + kw;
            float val = (ih >= 0 && ih < 64 && iw >= 0 && iw < 64) ? s[ic * 4096 + ih * 64 + iw] : 0.f;
            unsigned short h, l; bf16_split(val, h, l);
            t[j >> 1]        |= (uint32_t)h << ((j & 1) * 16);
            t[(j + 27) >> 1] |= (uint32_t)h << (((j + 27) & 1) * 16);
            t[(j + 54) >> 1] |= (uint32_t)l << (((j + 54) & 1) * 16);
        }
        uint4* row = (uint4*)(A + ((size_t)(img * 1024 + p)) * 128);
#pragma unroll
        for (int w = 0; w < 16; w++) row[w] = make_uint4(t[4*w], t[4*w+1], t[4*w+2], t[4*w+3]);
    }
}

// grid(256, 4): y handles 4 of the 16 ic-chunks
__global__ __launch_bounds__(256) void im2col2(const float* __restrict__ in, __nv_bfloat16* __restrict__ A)
{
    __shared__ float s[8192];
    int img = blockIdx.x, tid = threadIdx.x;
    int p = tid, oh = p >> 4, ow = p & 15;
    char* rowb = (char*)(A + ((size_t)(img * 256 + p)) * 2304);
    for (int ii = 0; ii < 4; ii++) {
        int icb = blockIdx.y * 4 + ii;
        __syncthreads();
        const float* ip = in + ((size_t)img * 128 + icb * 8) * 1024;
        for (int i = tid; i < 8192; i += 256) s[i] = ip[i];
        __syncthreads();
        uint32_t th[36], tl[36];
#pragma unroll
        for (int u = 0; u < 36; u++) {
            uint32_t hv = 0, lv = 0;
#pragma unroll
            for (int half = 0; half < 2; half++) {
                int j = 2 * u + half;
                int ic8 = j / 9, kk = j % 9, kh = kk / 3, kw = kk % 3;
                int ih = 2 * oh - 1 + kh, iw = 2 * ow - 1 + kw;
                float val = (ih >= 0 && ih < 32 && iw >= 0 && iw < 32) ? s[ic8 * 1024 + (ih << 5) + iw] : 0.f;
                unsigned short h, l; bf16_split(val, h, l);
                hv |= (uint32_t)h << (half * 16);
                lv |= (uint32_t)l << (half * 16);
            }
            th[u] = hv; tl[u] = lv;
        }
        uint4* oh4 = (uint4*)(rowb + icb * 144);
        uint4* ol4 = (uint4*)(rowb + 2304 + icb * 144);
#pragma unroll
        for (int w = 0; w < 9; w++) {
            oh4[w] = make_uint4(th[4*w], th[4*w+1], th[4*w+2], th[4*w+3]);
            ol4[w] = make_uint4(tl[4*w], tl[4*w+1], tl[4*w+2], tl[4*w+3]);
        }
    }
}

// grid(256, 2): y handles 4 of the 8 ic-chunks
__global__ __launch_bounds__(256) void im2col3(const float* __restrict__ in, __nv_bfloat16* __restrict__ A)
{
    __shared__ float s[8192];
    int img = blockIdx.x, tid = threadIdx.x;
    int p = tid & 63, q = tid >> 6;
    int oh = p >> 3, ow = p & 7;
    char* rowb = (char*)(A + ((size_t)(img * 64 + p)) * 4608);
    for (int ii = 0; ii < 4; ii++) {
        int icb = blockIdx.y * 4 + ii;
        __syncthreads();
        const float* ip = in + ((size_t)img * 256 + icb * 32) * 256;
        for (int i = tid; i < 8192; i += 256) s[i] = ip[i];
        __syncthreads();
        uint32_t th[36], tl[36];
#pragma unroll
        for (int u = 0; u < 36; u++) {
            uint32_t hv = 0, lv = 0;
#pragma unroll
            for (int half = 0; half < 2; half++) {
                int j = 2 * u + half;
                int ic8 = j / 9, kk = j % 9, kh = kk / 3, kw = kk % 3;
                int ih = 2 * oh - 1 + kh, iw = 2 * ow - 1 + kw;
                float val = (ih >= 0 && ih < 16 && iw >= 0 && iw < 16)
                                ? s[(q * 8 + ic8) * 256 + (ih << 4) + iw] : 0.f;
                unsigned short h, l; bf16_split(val, h, l);
                hv |= (uint32_t)h << (half * 16);
                lv |= (uint32_t)l << (half * 16);
            }
            th[u] = hv; tl[u] = lv;
        }
        uint4* oh4 = (uint4*)(rowb + icb * 576 + q * 144);
        uint4* ol4 = (uint4*)(rowb + 4608 + icb * 576 + q * 144);
#pragma unroll
        for (int w = 0; w < 9; w++) {
            oh4[w] = make_uint4(th[4*w], th[4*w+1], th[4*w+2], th[4*w+3]);
            ol4[w] = make_uint4(tl[4*w], tl[4*w+1], tl[4*w+2], tl[4*w+3]);
        }
    }
}

// ============================ HMMA GEMM (mma.sync bf16) ============================
// CONV==2 now uses BN=256 (full N in one block) to halve A DRAM traffic.
template<int CONV>
__global__ __launch_bounds__(256)
void gemm_kernel(const __nv_bfloat16* __restrict__ A, const __nv_bfloat16* __restrict__ Bw,
                 const float* __restrict__ bias, const float* __restrict__ g,
                 const float* __restrict__ beta, const float* __restrict__ m,
                 const float* __restrict__ v, float* __restrict__ out)
{
    constexpr int N  = (CONV == 2) ? 256 : ((CONV == 1) ? 128 : 64);
    constexpr int NC = (CONV == 1) ? 2 : ((CONV == 2) ? 54 : 108);
    constexpr int KS = (CONV == 1) ? 128 : ((CONV == 2) ? 2304 : 4608);
    constexpr int HC = (CONV == 1) ? 2 : ((CONV == 2) ? 18 : 36);
    constexpr int BN = N;                       // full N per block
    constexpr int WN = BN / 2;
    constexpr int NT = WN / 8;
    constexpr int ABUF = 128 * 144;
    constexpr int BBUF = BN * 144;
    constexpr int BGI = (BN * 8) / 256;
    constexpr int P = BN + 1;

    extern __shared__ __align__(16) char smem[];
    __shared__ float scs[256], shs[256];

    int tid = threadIdx.x, wid = tid >> 5, lane = tid & 31;
    int wm = wid & 3, wn = wid >> 2;
    int rowbase = blockIdx.x * 128;

    if (tid < N) {
        float sc = g[tid] / sqrtf(v[tid] + BN_EPS);
        scs[tid] = sc;
        shs[tid] = beta[tid] - m[tid] * sc + bias[tid] * sc;
    }

    uint32_t sb = smem_u32(smem);

    float acc[2][NT][4];
#pragma unroll
    for (int i = 0; i < 2; i++)
#pragma unroll
        for (int j = 0; j < NT; j++)
#pragma unroll
            for (int q = 0; q < 4; q++) acc[i][j][q] = 0.f;

    auto issue_copy = [&](int c) {
        int Ai = (c < HC) ? c : c - HC;
        int Bi = (c < 2 * HC) ? c : c - 2 * HC;
        int buf = c & 1;
        uint32_t ab = sb + buf * (ABUF + BBUF);
        uint32_t bb = ab + ABUF;
#pragma unroll
        for (int i = 0; i < 4; i++) {
            int gi = tid + 256 * i; int rr = gi >> 3, gc = gi & 7;
            cp_async16(ab + rr * 144 + gc * 16,
                       (const char*)A + ((size_t)(rowbase + rr) * KS + Ai * 64) * 2 + gc * 16);
        }
#pragma unroll
        for (int i = 0; i < BGI; i++) {
            int gi = tid + 256 * i; int rr = gi >> 3, gc = gi & 7;
            cp_async16(bb + rr * 144 + gc * 16,
                       (const char*)Bw + ((size_t)rr * KS + Bi * 64) * 2 + gc * 16);
        }
        asm volatile("cp.async.commit_group;");
    };

    issue_copy(0);
    for (int c = 0; c < NC; c++) {
        if (c + 1 < NC) {
            issue_copy(c + 1);
            asm volatile("cp.async.wait_group 1;");
        } else {
            asm volatile("cp.async.wait_group 0;");
        }
        __syncthreads();

        int buf = c & 1;
        uint32_t ab = sb + buf * (ABUF + BBUF);
        uint32_t bb = ab + ABUF;
#pragma unroll
        for (int ks = 0; ks < 4; ks++) {
            uint32_t af[2][4];
#pragma unroll
            for (int mt = 0; mt < 2; mt++) {
                uint32_t addr = ab + (wm * 32 + mt * 16 + (lane & 15)) * 144
                                + ks * 32 + ((lane >> 4) << 4);
                ldsm_x4(af[mt], addr);
            }
#pragma unroll
            for (int nt2 = 0; nt2 < NT / 2; nt2++) {
                uint32_t bf[4];
                uint32_t addr = bb + (wn * WN + nt2 * 16 + (lane & 7) + (((lane >> 4) & 1) << 3)) * 144
                                + ks * 32 + (((lane >> 3) & 1) << 4);
                ldsm_x4(bf, addr);
#pragma unroll
                for (int mt = 0; mt < 2; mt++) {
                    mma_bf16(acc[mt][2 * nt2],     af[mt], bf);
                    mma_bf16(acc[mt][2 * nt2 + 1], af[mt], bf + 2);
                }
            }
        }
        __syncthreads();
    }

    float* stage = (float*)smem;
#pragma unroll
    for (int mt = 0; mt < 2; mt++)
#pragma unroll
        for (int nt = 0; nt < NT; nt++) {
            int r0 = wm * 32 + mt * 16 + (lane >> 2);
            int c0 = wn * WN + nt * 8 + 2 * (lane & 3);
            stage[r0 * P + c0]           = acc[mt][nt][0];
            stage[r0 * P + c0 + 1]       = acc[mt][nt][1];
            stage[(r0 + 8) * P + c0]     = acc[mt][nt][2];
            stage[(r0 + 8) * P + c0 + 1] = acc[mt][nt][3];
        }
    __syncthreads();

#pragma unroll
    for (int j = 0; j < BN / 8; j++) {
        int colL = wid * (BN / 8) + j;
        int gcol = colL;
        float sc = scs[gcol], sh = shs[gcol];
#pragma unroll
        for (int it = 0; it < 4; it++) {
            int r = it * 32 + lane;
            float y = stage[r * P + colL] * sc + sh;
            y = y > 0.f ? y : SLOPE * y;
            int grow = rowbase + r;
            if (CONV == 1) {
                int img = grow >> 10, p = grow & 1023;
                out[((size_t)(img * 128 + gcol)) * 1024 + p] = y;
            } else if (CONV == 2) {
                int img = grow >> 8, p = grow & 255;
                out[((size_t)(img * 256 + gcol)) * 256 + p] = y;
            } else {
                int img = grow >> 6, p = grow & 63;
                out[(size_t)img * 4096 + gcol * 64 + p] = y;
            }
        }
    }
}

// ============================ k-means ============================
__global__ __launch_bounds__(256) void normalize_kernel(float* __restrict__ data)
{
    int row = blockIdx.x, tid = threadIdx.x;
    float* dr = data + row * 4096;
    float vals[16];
    float s = 0.f;
#pragma unroll
    for (int i = 0; i < 16; i++) { vals[i] = dr[tid + i * 256]; s = fmaf(vals[i], vals[i], s); }
    __shared__ float sm[9];
    int lane = tid & 31, warp = tid >> 5;
#pragma unroll
    for (int off = 16; off > 0; off >>= 1) s += __shfl_down_sync(0xffffffffu, s, off);
    if (lane == 0) sm[warp] = s;
    __syncthreads();
    if (tid == 0) {
        float t = 0.f;
        for (int w = 0; w < 8; w++) t += sm[w];
        sm[8] = 1.f / sqrtf(t);
    }
    __syncthreads();
    float inv = sm[8];
#pragma unroll
    for (int i = 0; i < 16; i++) dr[tid + i * 256] = vals[i] * inv;
}

// G = data @ data^T  (256x256, K=4096). grid(16,16), block 256 = 16x16.
__global__ __launch_bounds__(256) void gram_kernel(const float* __restrict__ data, float* __restrict__ G)
{
    __shared__ float at[16][129];
    __shared__ float bt[16][129];
    int tid = threadIdx.x;
    int ty = tid >> 4, tx = tid & 15;
    int r0 = blockIdx.y * 16, c0 = blockIdx.x * 16;
    float acc = 0.f;
    for (int kc = 0; kc < 4096; kc += 128) {
        __syncthreads();
        for (int i = tid; i < 2048; i += 256) {
            int rr = i >> 7, cc = i & 127;
            at[rr][cc] = data[(size_t)(r0 + rr) * 4096 + kc + cc];
            bt[rr][cc] = data[(size_t)(c0 + rr) * 4096 + kc + cc];
        }
        __syncthreads();
#pragma unroll 16
        for (int k = 0; k < 128; k++) acc = fmaf(at[ty][k], bt[tx][k], acc);
    }
    G[(r0 + ty) * 256 + c0 + tx] = acc;
}

// D0 = data @ mu0^T (raw dots). grid(256), block(256).
__global__ __launch_bounds__(256) void dist0_kernel(
    const float* __restrict__ data, const float* __restrict__ mu, float* __restrict__ dout)
{
    int row = blockIdx.x, tid = threadIdx.x;
    const float* dr = data + row * 4096;
    float acc[16];
#pragma unroll
    for (int k = 0; k < 16; k++) acc[k] = 0.f;
#pragma unroll 4
    for (int i = 0; i < 16; i++) {
        int j = tid + i * 256;
        float dj = __ldg(dr + j);
#pragma unroll
        for (int k = 0; k < 16; k++) acc[k] = fmaf(dj, __ldg(mu + k * 4096 + j), acc[k]);
    }
    __shared__ float wsum[8][16];
    int lane = tid & 31, warp = tid >> 5;
#pragma unroll
    for (int k = 0; k < 16; k++) {
        float vv = acc[k];
#pragma unroll
        for (int off = 16; off > 0; off >>= 1) vv += __shfl_down_sync(0xffffffffu, vv, off);
        if (lane == 0) wsum[warp][k] = vv;
    }
    __syncthreads();
    if (tid < 16) {
        float s = 0.f;
#pragma unroll
        for (int w = 0; w < 8; w++) s += wsum[w][tid];
        dout[row * 16 + tid] = s;
    }
}

// All 12 softmax steps + 11 mu-updates in one block via dist = G @ (r / colsum).
// 1024 threads: row = tid>>2 (256), kg = tid&3 (4 k each).
__global__ __launch_bounds__(1024) void kmeans_iter_kernel(
    const float* __restrict__ G, const float* __restrict__ D0, float* __restrict__ out)
{
    __shared__ float rD[256 * 16];
    __shared__ float part[32][16];
    __shared__ float invcs[16];
    int tid = threadIdx.x;
    int row = tid >> 2, kg = tid & 3;

    for (int it = 0; it < 12; it++) {
        float L[4];
        if (it == 0) {
#pragma unroll
            for (int i = 0; i < 4; i++) L[i] = CT * D0[row * 16 + kg * 4 + i];
        } else {
            float a0 = 0.f, a1 = 0.f, a2 = 0.f, a3 = 0.f;
            const float4* gr = (const float4*)(G + (size_t)row * 256);
            const float4* rp = (const float4*)&rD[kg * 4];
#pragma unroll 8
            for (int n4 = 0; n4 < 64; n4++) {
                float4 gv = __ldg(gr + n4);
                float4 r0 = rp[n4 * 16];
                float4 r1 = rp[n4 * 16 + 4];
                float4 r2 = rp[n4 * 16 + 8];
                float4 r3 = rp[n4 * 16 + 12];
                a0 += gv.x * r0.x + gv.y * r1.x + gv.z * r2.x + gv.w * r3.x;
                a1 += gv.x * r0.y + gv.y * r1.y + gv.z * r2.y + gv.w * r3.y;
                a2 += gv.x * r0.z + gv.y * r1.z + gv.z * r2.z + gv.w * r3.z;
                a3 += gv.x * r0.w + gv.y * r1.w + gv.z * r2.w + gv.w * r3.w;
            }
            L[0] = CT * a0; L[1] = CT * a1; L[2] = CT * a2; L[3] = CT * a3;
        }
        float mx = fmaxf(fmaxf(L[0], L[1]), fmaxf(L[2], L[3]));
        mx = fmaxf(mx, __shfl_xor_sync(0xffffffffu, mx, 1));
        mx = fmaxf(mx, __shfl_xor_sync(0xffffffffu, mx, 2));
        float e[4]; float s = 0.f;
#pragma unroll
        for (int i = 0; i < 4; i++) { e[i] = expf(L[i] - mx); s += e[i]; }
        s += __shfl_xor_sync(0xffffffffu, s, 1);
        s += __shfl_xor_sync(0xffffffffu, s, 2);
        float inv = 1.f / s;
#pragma unroll
        for (int i = 0; i < 4; i++) e[i] *= inv;

        if (it == 11) {
            *(float4*)&out[row * 16 + kg * 4] = make_float4(e[0], e[1], e[2], e[3]);
            return;
        }
        __syncthreads();   // previous-iter rD reads complete before overwrite
        *(float4*)&rD[row * 16 + kg * 4] = make_float4(e[0], e[1], e[2], e[3]);
        __syncthreads();
        if (tid < 512) {
            int k = tid & 15, grp = tid >> 4;
            float ss = 0.f;
#pragma unroll
            for (int n = 0; n < 8; n++) ss += rD[(grp * 8 + n) * 16 + k];
            part[grp][k] = ss;
        }
        __syncthreads();
        if (tid < 16) {
            float ss = 0.f;
#pragma unroll
            for (int gq = 0; gq < 32; gq++) ss += part[gq][tid];
            invcs[tid] = 1.f / ss;
        }
        __syncthreads();
#pragma unroll
        for (int i = 0; i < 4; i++)
            rD[row * 16 + kg * 4 + i] = e[i] * invcs[kg * 4 + i];
        __syncthreads();
    }
}

// ============================ host ============================
extern "C" void kernel_launch(void* const* d_in, const int* in_sizes, int n_in,
                              void* d_out, int out_size)
{
    const float* x   = (const float*)d_in[0];
    const float* w1  = (const float*)d_in[1];
    const float* b1  = (const float*)d_in[2];
    const float* g1  = (const float*)d_in[3];
    const float* be1 = (const float*)d_in[4];
    const float* m1  = (const float*)d_in[5];
    const float* v1  = (const float*)d_in[6];
    const float* w2  = (const float*)d_in[7];
    const float* b2  = (const float*)d_in[8];
    const float* g2  = (const float*)d_in[9];
    const float* be2 = (const float*)d_in[10];
    const float* m2  = (const float*)d_in[11];
    const float* v2  = (const float*)d_in[12];
    const float* w3  = (const float*)d_in[13];
    const float* b3  = (const float*)d_in[14];
    const float* g3  = (const float*)d_in[15];
    const float* be3 = (const float*)d_in[16];
    const float* m3  = (const float*)d_in[17];
    const float* v3  = (const float*)d_in[18];
    const float* mu0 = (const float*)d_in[19];

    float *h1, *h2, *data, *G, *D0;
    __nv_bfloat16 *A1, *A2, *A3, *B1, *B2, *B3;
    cudaGetSymbolAddress((void**)&h1, g_h1);
    cudaGetSymbolAddress((void**)&h2, g_h2);
    cudaGetSymbolAddress((void**)&data, g_data);
    cudaGetSymbolAddress((void**)&G, g_G);
    cudaGetSymbolAddress((void**)&D0, g_D0);
    cudaGetSymbolAddress((void**)&A1, g_A1);
    cudaGetSymbolAddress((void**)&A2, g_A2);
    cudaGetSymbolAddress((void**)&A3, g_A3);
    cudaGetSymbolAddress((void**)&B1, g_B1);
    cudaGetSymbolAddress((void**)&B2, g_B2);
    cudaGetSymbolAddress((void**)&B3, g_B3);

    const int smem_g1 = 2 * (128 * 144 + 128 * 144);               // 73728
    const int smem_g2 = 128 * 257 * 4;                             // 131584 (stage > loop 110592)
    const int smem_g3 = 2 * (128 * 144 + 64 * 144);                // 55296
    cudaFuncSetAttribute(gemm_kernel<1>, cudaFuncAttributeMaxDynamicSharedMemorySize, smem_g1);
    cudaFuncSetAttribute(gemm_kernel<2>, cudaFuncAttributeMaxDynamicSharedMemorySize, smem_g2);
    cudaFuncSetAttribute(gemm_kernel<3>, cudaFuncAttributeMaxDynamicSharedMemorySize, smem_g3);

    prep_w1<<<1, 128>>>(w1, B1);
    prep_w2<<<256, 256>>>(w2, B2);
    prep_w3<<<64, 256>>>(w3, B3);

    im2col1<<<256, 256>>>(x, A1);
    gemm_kernel<1><<<dim3(2048, 1), 256, smem_g1>>>(A1, B1, b1, g1, be1, m1, v1, h1);
    im2col2<<<dim3(256, 4), 256>>>(h1, A2);
    gemm_kernel<2><<<dim3(512, 1), 256, smem_g2>>>(A2, B2, b2, g2, be2, m2, v2, h2);
    im2col3<<<dim3(256, 2), 256>>>(h2, A3);
    gemm_kernel<3><<<dim3(128, 1), 256, smem_g3>>>(A3, B3, b3, g3, be3, m3, v3, data);

    normalize_kernel<<<256, 256>>>(data);
    gram_kernel<<<dim3(16, 16), 256>>>(data, G);
    dist0_kernel<<<256, 256>>>(data, mu0, D0);
    kmeans_iter_kernel<<<1, 1024>>>(G, D0, (float*)d_out);
}

// round 9
// speedup vs baseline: 1.7422x; 1.4271x over previous
#include <cuda_runtime.h>
#include <cuda_fp16.h>
#include <math.h>
#include <stdint.h>

#define BN_EPS 1e-3f
#define SLOPE  0.1f
#define CT     30.0f

// ============================ scratch globals ============================
__device__ float g_h1[256 * 128 * 1024];
__device__ float g_h2[256 * 256 * 256];
__device__ float g_data[256 * 4096];
__device__ float g_G[256 * 256];
__device__ float g_D0[256 * 16];
__device__ __half g_A1[256 * 1024 * 64];      // fp16 im2col conv1 (K=64: hi27|hi27|pad)
__device__ __half g_A2[65536ull * 1152];      // fp16 im2col conv2
__device__ __half g_A3[16384ull * 2304];      // fp16 im2col conv3
__device__ __half g_B1[128 * 64];             // w1 [hi27|lo27|pad]
__device__ __half g_B2[256 * 2304];           // w2 [hi1152|lo1152]
__device__ __half g_B3[64 * 4608];            // w3 [hi2304|lo2304]

__device__ __forceinline__ void fp16_split(float x, unsigned short& h, unsigned short& l) {
    __half hb = __float2half_rn(x);
    h = __half_as_ushort(hb);
    l = __half_as_ushort(__float2half_rn(x - __half2float(hb)));
}
__device__ __forceinline__ uint32_t smem_u32(const void* p) {
    uint32_t a;
    asm("{ .reg .u64 t; cvta.to.shared.u64 t, %1; cvt.u32.u64 %0, t; }" : "=r"(a) : "l"(p));
    return a;
}
__device__ __forceinline__ void cp_async16(uint32_t dst, const void* src) {
    asm volatile("cp.async.cg.shared.global [%0], [%1], 16;" :: "r"(dst), "l"(src));
}
__device__ __forceinline__ void ldsm_x4(uint32_t* f, uint32_t addr) {
    asm volatile("ldmatrix.sync.aligned.m8n8.x4.shared.b16 {%0,%1,%2,%3}, [%4];"
                 : "=r"(f[0]), "=r"(f[1]), "=r"(f[2]), "=r"(f[3]) : "r"(addr));
}
__device__ __forceinline__ void mma_f16(float* d, const uint32_t* a, const uint32_t* b) {
    asm volatile(
        "mma.sync.aligned.m16n8k16.row.col.f32.f16.f16.f32 "
        "{%0,%1,%2,%3}, {%4,%5,%6,%7}, {%8,%9}, {%0,%1,%2,%3};"
        : "+f"(d[0]), "+f"(d[1]), "+f"(d[2]), "+f"(d[3])
        : "r"(a[0]), "r"(a[1]), "r"(a[2]), "r"(a[3]), "r"(b[0]), "r"(b[1]));
}

// ============================ weight prep ============================
__global__ __launch_bounds__(128) void prep_w1(const float* __restrict__ w, __half* __restrict__ o)
{
    int oc = threadIdx.x;
    __half* row = o + oc * 64;
#pragma unroll
    for (int j = 0; j < 64; j++) row[j] = __ushort_as_half((unsigned short)0);
#pragma unroll
    for (int j = 0; j < 27; j++) {
        unsigned short h, l; fp16_split(w[oc * 27 + j], h, l);
        row[j]      = __ushort_as_half(h);
        row[27 + j] = __ushort_as_half(l);
    }
}
__global__ __launch_bounds__(256) void prep_w2(const float* __restrict__ w, __half* __restrict__ o)
{
    int oc = blockIdx.x;
    for (int k = threadIdx.x; k < 1152; k += 256) {
        unsigned short h, l; fp16_split(w[oc * 1152 + k], h, l);
        o[oc * 2304 + k] = __ushort_as_half(h);
        o[oc * 2304 + 1152 + k] = __ushort_as_half(l);
    }
}
__global__ __launch_bounds__(256) void prep_w3(const float* __restrict__ w, __half* __restrict__ o)
{
    int oc = blockIdx.x;
    for (int k = threadIdx.x; k < 2304; k += 256) {
        unsigned short h, l; fp16_split(w[oc * 2304 + k], h, l);
        o[oc * 4608 + k] = __ushort_as_half(h);
        o[oc * 4608 + 2304 + k] = __ushort_as_half(l);
    }
}

// ============================ im2col (single fp16) ============================
__global__ __launch_bounds__(256) void im2col1(const float* __restrict__ x, __half* __restrict__ A)
{
    __shared__ float s[12288];
    int img = blockIdx.x, tid = threadIdx.x;
    const float* xin = x + img * 12288;
    for (int i = tid; i < 12288; i += 256) s[i] = xin[i];
    __syncthreads();
#pragma unroll
    for (int pp = 0; pp < 4; pp++) {
        int p = tid + pp * 256;
        int oh = p >> 5, ow = p & 31;
        uint32_t t[32];
#pragma unroll
        for (int i = 0; i < 32; i++) t[i] = 0;
#pragma unroll
        for (int j = 0; j < 27; j++) {
            int ic = j / 9, kk = j % 9, kh = kk / 3, kw = kk % 3;
            int ih = 2 * oh - 1 + kh, iw = 2 * ow - 1 + kw;
            float val = (ih >= 0 && ih < 64 && iw >= 0 && iw < 64) ? s[ic * 4096 + ih * 64 + iw] : 0.f;
            unsigned short h = __half_as_ushort(__float2half_rn(val));
            t[j >> 1]        |= (uint32_t)h << ((j & 1) * 16);
            int jj = j + 27;
            t[jj >> 1]       |= (uint32_t)h << ((jj & 1) * 16);
        }
        uint4* row = (uint4*)(A + ((size_t)(img * 1024 + p)) * 64);
#pragma unroll
        for (int w = 0; w < 8; w++) row[w] = make_uint4(t[4*w], t[4*w+1], t[4*w+2], t[4*w+3]);
    }
}

// grid(256, 4): y handles 4 of the 16 ic-chunks
__global__ __launch_bounds__(256) void im2col2(const float* __restrict__ in, __half* __restrict__ A)
{
    __shared__ float s[8192];
    int img = blockIdx.x, tid = threadIdx.x;
    int p = tid, oh = p >> 4, ow = p & 15;
    char* rowb = (char*)(A + ((size_t)(img * 256 + p)) * 1152);
    for (int ii = 0; ii < 4; ii++) {
        int icb = blockIdx.y * 4 + ii;
        __syncthreads();
        const float* ip = in + ((size_t)img * 128 + icb * 8) * 1024;
        for (int i = tid; i < 8192; i += 256) s[i] = ip[i];
        __syncthreads();
        uint32_t th[36];
#pragma unroll
        for (int u = 0; u < 36; u++) {
            uint32_t hv = 0;
#pragma unroll
            for (int half = 0; half < 2; half++) {
                int j = 2 * u + half;
                int ic8 = j / 9, kk = j % 9, kh = kk / 3, kw = kk % 3;
                int ih = 2 * oh - 1 + kh, iw = 2 * ow - 1 + kw;
                float val = (ih >= 0 && ih < 32 && iw >= 0 && iw < 32) ? s[ic8 * 1024 + (ih << 5) + iw] : 0.f;
                hv |= (uint32_t)__half_as_ushort(__float2half_rn(val)) << (half * 16);
            }
            th[u] = hv;
        }
        uint4* oh4 = (uint4*)(rowb + icb * 144);
#pragma unroll
        for (int w = 0; w < 9; w++)
            oh4[w] = make_uint4(th[4*w], th[4*w+1], th[4*w+2], th[4*w+3]);
    }
}

// grid(256, 2): y handles 4 of the 8 staged 32-ic chunks
__global__ __launch_bounds__(256) void im2col3(const float* __restrict__ in, __half* __restrict__ A)
{
    __shared__ float s[8192];
    int img = blockIdx.x, tid = threadIdx.x;
    int p = tid & 63, q = tid >> 6;
    int oh = p >> 3, ow = p & 7;
    char* rowb = (char*)(A + ((size_t)(img * 64 + p)) * 2304);
    for (int ii = 0; ii < 4; ii++) {
        int icb = blockIdx.y * 4 + ii;
        __syncthreads();
        const float* ip = in + ((size_t)img * 256 + icb * 32) * 256;
        for (int i = tid; i < 8192; i += 256) s[i] = ip[i];
        __syncthreads();
        uint32_t th[36];
#pragma unroll
        for (int u = 0; u < 36; u++) {
            uint32_t hv = 0;
#pragma unroll
            for (int half = 0; half < 2; half++) {
                int j = 2 * u + half;
                int ic8 = j / 9, kk = j % 9, kh = kk / 3, kw = kk % 3;
                int ih = 2 * oh - 1 + kh, iw = 2 * ow - 1 + kw;
                float val = (ih >= 0 && ih < 16 && iw >= 0 && iw < 16)
                                ? s[(q * 8 + ic8) * 256 + (ih << 4) + iw] : 0.f;
                hv |= (uint32_t)__half_as_ushort(__float2half_rn(val)) << (half * 16);
            }
            th[u] = hv;
        }
        uint4* oh4 = (uint4*)(rowb + icb * 576 + q * 144);
#pragma unroll
        for (int w = 0; w < 9; w++)
            oh4[w] = make_uint4(th[4*w], th[4*w+1], th[4*w+2], th[4*w+3]);
    }
}

// ============================ HMMA GEMM (mma.sync fp16, 2-term weight split) ============================
// chunk schedule: Ai = c>>1 (each A chunk reused for Bh then Bl); Bi = (c&1)*HC + (c>>1)
// A double-buffered at PAIR granularity (copy only on even c), B per-chunk.
template<int CONV>
__global__ __launch_bounds__(256)
void gemm_kernel(const __half* __restrict__ A, const __half* __restrict__ Bw,
                 const float* __restrict__ bias, const float* __restrict__ g,
                 const float* __restrict__ beta, const float* __restrict__ m,
                 const float* __restrict__ v, float* __restrict__ out)
{
    constexpr int N   = (CONV == 2) ? 256 : ((CONV == 1) ? 128 : 64);
    constexpr int KS  = (CONV == 1) ? 64 : ((CONV == 2) ? 1152 : 2304);   // A row length
    constexpr int BKS = (CONV == 1) ? 64 : 2 * KS;                        // B row length
    constexpr int HC  = (CONV == 1) ? 1 : KS / 64;
    constexpr int NC  = (CONV == 1) ? 1 : 2 * HC;
    constexpr int BN = N;
    constexpr int WN = BN / 2;
    constexpr int NT = WN / 8;
    constexpr int ABUF = 128 * 144;
    constexpr int BBUF = BN * 144;
    constexpr int BGI = (BN * 8) / 256;
    constexpr int P = BN + 1;

    extern __shared__ __align__(16) char smem[];
    __shared__ float scs[256], shs[256];

    int tid = threadIdx.x, wid = tid >> 5, lane = tid & 31;
    int wm = wid & 3, wn = wid >> 2;
    int rowbase = blockIdx.x * 128;

    if (tid < N) {
        float sc = g[tid] / sqrtf(v[tid] + BN_EPS);
        scs[tid] = sc;
        shs[tid] = beta[tid] - m[tid] * sc + bias[tid] * sc;
    }

    uint32_t sb = smem_u32(smem);
    const uint32_t sbB = sb + 2 * ABUF;

    float acc[2][NT][4];
#pragma unroll
    for (int i = 0; i < 2; i++)
#pragma unroll
        for (int j = 0; j < NT; j++)
#pragma unroll
            for (int q = 0; q < 4; q++) acc[i][j][q] = 0.f;

    auto issue_copy = [&](int c) {
        int Ai = c >> 1;
        int Bi = (c & 1) * HC + (c >> 1);
        if ((c & 1) == 0) {
            uint32_t ab = sb + ((c >> 1) & 1) * ABUF;
#pragma unroll
            for (int i = 0; i < 4; i++) {
                int gi = tid + 256 * i; int rr = gi >> 3, gc = gi & 7;
                cp_async16(ab + rr * 144 + gc * 16,
                           (const char*)A + ((size_t)(rowbase + rr) * KS + Ai * 64) * 2 + gc * 16);
            }
        }
        uint32_t bb = sbB + (c & 1) * BBUF;
#pragma unroll
        for (int i = 0; i < BGI; i++) {
            int gi = tid + 256 * i; int rr = gi >> 3, gc = gi & 7;
            cp_async16(bb + rr * 144 + gc * 16,
                       (const char*)Bw + ((size_t)rr * BKS + Bi * 64) * 2 + gc * 16);
        }
        asm volatile("cp.async.commit_group;");
    };

    issue_copy(0);
    for (int c = 0; c < NC; c++) {
        if (c + 1 < NC) {
            issue_copy(c + 1);
            asm volatile("cp.async.wait_group 1;");
        } else {
            asm volatile("cp.async.wait_group 0;");
        }
        __syncthreads();

        uint32_t ab = sb + ((c >> 1) & 1) * ABUF;
        uint32_t bb = sbB + (c & 1) * BBUF;
#pragma unroll
        for (int ks = 0; ks < 4; ks++) {
            uint32_t af[2][4];
#pragma unroll
            for (int mt = 0; mt < 2; mt++) {
                uint32_t addr = ab + (wm * 32 + mt * 16 + (lane & 15)) * 144
                                + ks * 32 + ((lane >> 4) << 4);
                ldsm_x4(af[mt], addr);
            }
#pragma unroll
            for (int nt2 = 0; nt2 < NT / 2; nt2++) {
                uint32_t bf[4];
                uint32_t addr = bb + (wn * WN + nt2 * 16 + (lane & 7) + (((lane >> 4) & 1) << 3)) * 144
                                + ks * 32 + (((lane >> 3) & 1) << 4);
                ldsm_x4(bf, addr);
#pragma unroll
                for (int mt = 0; mt < 2; mt++) {
                    mma_f16(acc[mt][2 * nt2],     af[mt], bf);
                    mma_f16(acc[mt][2 * nt2 + 1], af[mt], bf + 2);
                }
            }
        }
        __syncthreads();
    }

    float* stage = (float*)smem;
#pragma unroll
    for (int mt = 0; mt < 2; mt++)
#pragma unroll
        for (int nt = 0; nt < NT; nt++) {
            int r0 = wm * 32 + mt * 16 + (lane >> 2);
            int c0 = wn * WN + nt * 8 + 2 * (lane & 3);
            stage[r0 * P + c0]           = acc[mt][nt][0];
            stage[r0 * P + c0 + 1]       = acc[mt][nt][1];
            stage[(r0 + 8) * P + c0]     = acc[mt][nt][2];
            stage[(r0 + 8) * P + c0 + 1] = acc[mt][nt][3];
        }
    __syncthreads();

#pragma unroll
    for (int j = 0; j < BN / 8; j++) {
        int colL = wid * (BN / 8) + j;
        float sc = scs[colL], sh = shs[colL];
#pragma unroll
        for (int it = 0; it < 4; it++) {
            int r = it * 32 + lane;
            float y = stage[r * P + colL] * sc + sh;
            y = y > 0.f ? y : SLOPE * y;
            int grow = rowbase + r;
            if (CONV == 1) {
                int img = grow >> 10, p = grow & 1023;
                out[((size_t)(img * 128 + colL)) * 1024 + p] = y;
            } else if (CONV == 2) {
                int img = grow >> 8, p = grow & 255;
                out[((size_t)(img * 256 + colL)) * 256 + p] = y;
            } else {
                int img = grow >> 6, p = grow & 63;
                out[(size_t)img * 4096 + colL * 64 + p] = y;
            }
        }
    }
}

// ============================ k-means ============================
__global__ __launch_bounds__(256) void normalize_kernel(float* __restrict__ data)
{
    int row = blockIdx.x, tid = threadIdx.x;
    float* dr = data + row * 4096;
    float vals[16];
    float s = 0.f;
#pragma unroll
    for (int i = 0; i < 16; i++) { vals[i] = dr[tid + i * 256]; s = fmaf(vals[i], vals[i], s); }
    __shared__ float sm[9];
    int lane = tid & 31, warp = tid >> 5;
#pragma unroll
    for (int off = 16; off > 0; off >>= 1) s += __shfl_down_sync(0xffffffffu, s, off);
    if (lane == 0) sm[warp] = s;
    __syncthreads();
    if (tid == 0) {
        float t = 0.f;
        for (int w = 0; w < 8; w++) t += sm[w];
        sm[8] = 1.f / sqrtf(t);
    }
    __syncthreads();
    float inv = sm[8];
#pragma unroll
    for (int i = 0; i < 16; i++) dr[tid + i * 256] = vals[i] * inv;
}

__global__ __launch_bounds__(256) void gram_kernel(const float* __restrict__ data, float* __restrict__ G)
{
    __shared__ float at[16][129];
    __shared__ float bt[16][129];
    int tid = threadIdx.x;
    int ty = tid >> 4, tx = tid & 15;
    int r0 = blockIdx.y * 16, c0 = blockIdx.x * 16;
    float acc = 0.f;
    for (int kc = 0; kc < 4096; kc += 128) {
        __syncthreads();
        for (int i = tid; i < 2048; i += 256) {
            int rr = i >> 7, cc = i & 127;
            at[rr][cc] = data[(size_t)(r0 + rr) * 4096 + kc + cc];
            bt[rr][cc] = data[(size_t)(c0 + rr) * 4096 + kc + cc];
        }
        __syncthreads();
#pragma unroll 16
        for (int k = 0; k < 128; k++) acc = fmaf(at[ty][k], bt[tx][k], acc);
    }
    G[(r0 + ty) * 256 + c0 + tx] = acc;
}

__global__ __launch_bounds__(256) void dist0_kernel(
    const float* __restrict__ data, const float* __restrict__ mu, float* __restrict__ dout)
{
    int row = blockIdx.x, tid = threadIdx.x;
    const float* dr = data + row * 4096;
    float acc[16];
#pragma unroll
    for (int k = 0; k < 16; k++) acc[k] = 0.f;
#pragma unroll 4
    for (int i = 0; i < 16; i++) {
        int j = tid + i * 256;
        float dj = __ldg(dr + j);
#pragma unroll
        for (int k = 0; k < 16; k++) acc[k] = fmaf(dj, __ldg(mu + k * 4096 + j), acc[k]);
    }
    __shared__ float wsum[8][16];
    int lane = tid & 31, warp = tid >> 5;
#pragma unroll
    for (int k = 0; k < 16; k++) {
        float vv = acc[k];
#pragma unroll
        for (int off = 16; off > 0; off >>= 1) vv += __shfl_down_sync(0xffffffffu, vv, off);
        if (lane == 0) wsum[warp][k] = vv;
    }
    __syncthreads();
    if (tid < 16) {
        float s = 0.f;
#pragma unroll
        for (int w = 0; w < 8; w++) s += wsum[w][tid];
        dout[row * 16 + tid] = s;
    }
}

__global__ __launch_bounds__(1024) void kmeans_iter_kernel(
    const float* __restrict__ G, const float* __restrict__ D0, float* __restrict__ out)
{
    __shared__ float rD[256 * 16];
    __shared__ float part[32][16];
    __shared__ float invcs[16];
    int tid = threadIdx.x;
    int row = tid >> 2, kg = tid & 3;

    for (int it = 0; it < 12; it++) {
        float L[4];
        if (it == 0) {
#pragma unroll
            for (int i = 0; i < 4; i++) L[i] = CT * D0[row * 16 + kg * 4 + i];
        } else {
            float a0 = 0.f, a1 = 0.f, a2 = 0.f, a3 = 0.f;
            const float4* gr = (const float4*)(G + (size_t)row * 256);
            const float4* rp = (const float4*)&rD[kg * 4];
#pragma unroll 8
            for (int n4 = 0; n4 < 64; n4++) {
                float4 gv = __ldg(gr + n4);
                float4 r0 = rp[n4 * 16];
                float4 r1 = rp[n4 * 16 + 4];
                float4 r2 = rp[n4 * 16 + 8];
                float4 r3 = rp[n4 * 16 + 12];
                a0 += gv.x * r0.x + gv.y * r1.x + gv.z * r2.x + gv.w * r3.x;
                a1 += gv.x * r0.y + gv.y * r1.y + gv.z * r2.y + gv.w * r3.y;
                a2 += gv.x * r0.z + gv.y * r1.z + gv.z * r2.z + gv.w * r3.z;
                a3 += gv.x * r0.w + gv.y * r1.w + gv.z * r2.w + gv.w * r3.w;
            }
            L[0] = CT * a0; L[1] = CT * a1; L[2] = CT * a2; L[3] = CT * a3;
        }
        float mx = fmaxf(fmaxf(L[0], L[1]), fmaxf(L[2], L[3]));
        mx = fmaxf(mx, __shfl_xor_sync(0xffffffffu, mx, 1));
        mx = fmaxf(mx, __shfl_xor_sync(0xffffffffu, mx, 2));
        float e[4]; float s = 0.f;
#pragma unroll
        for (int i = 0; i < 4; i++) { e[i] = expf(L[i] - mx); s += e[i]; }
        s += __shfl_xor_sync(0xffffffffu, s, 1);
        s += __shfl_xor_sync(0xffffffffu, s, 2);
        float inv = 1.f / s;
#pragma unroll
        for (int i = 0; i < 4; i++) e[i] *= inv;

        if (it == 11) {
            *(float4*)&out[row * 16 + kg * 4] = make_float4(e[0], e[1], e[2], e[3]);
            return;
        }
        __syncthreads();
        *(float4*)&rD[row * 16 + kg * 4] = make_float4(e[0], e[1], e[2], e[3]);
        __syncthreads();
        if (tid < 512) {
            int k = tid & 15, grp = tid >> 4;
            float ss = 0.f;
#pragma unroll
            for (int n = 0; n < 8; n++) ss += rD[(grp * 8 + n) * 16 + k];
            part[grp][k] = ss;
        }
        __syncthreads();
        if (tid < 16) {
            float ss = 0.f;
#pragma unroll
            for (int gq = 0; gq < 32; gq++) ss += part[gq][tid];
            invcs[tid] = 1.f / ss;
        }
        __syncthreads();
#pragma unroll
        for (int i = 0; i < 4; i++)
            rD[row * 16 + kg * 4 + i] = e[i] * invcs[kg * 4 + i];
        __syncthreads();
    }
}

// ============================ host ============================
extern "C" void kernel_launch(void* const* d_in, const int* in_sizes, int n_in,
                              void* d_out, int out_size)
{
    const float* x   = (const float*)d_in[0];
    const float* w1  = (const float*)d_in[1];
    const float* b1  = (const float*)d_in[2];
    const float* g1  = (const float*)d_in[3];
    const float* be1 = (const float*)d_in[4];
    const float* m1  = (const float*)d_in[5];
    const float* v1  = (const float*)d_in[6];
    const float* w2  = (const float*)d_in[7];
    const float* b2  = (const float*)d_in[8];
    const float* g2  = (const float*)d_in[9];
    const float* be2 = (const float*)d_in[10];
    const float* m2  = (const float*)d_in[11];
    const float* v2  = (const float*)d_in[12];
    const float* w3  = (const float*)d_in[13];
    const float* b3  = (const float*)d_in[14];
    const float* g3  = (const float*)d_in[15];
    const float* be3 = (const float*)d_in[16];
    const float* m3  = (const float*)d_in[17];
    const float* v3  = (const float*)d_in[18];
    const float* mu0 = (const float*)d_in[19];

    float *h1, *h2, *data, *G, *D0;
    __half *A1, *A2, *A3, *B1, *B2, *B3;
    cudaGetSymbolAddress((void**)&h1, g_h1);
    cudaGetSymbolAddress((void**)&h2, g_h2);
    cudaGetSymbolAddress((void**)&data, g_data);
    cudaGetSymbolAddress((void**)&G, g_G);
    cudaGetSymbolAddress((void**)&D0, g_D0);
    cudaGetSymbolAddress((void**)&A1, g_A1);
    cudaGetSymbolAddress((void**)&A2, g_A2);
    cudaGetSymbolAddress((void**)&A3, g_A3);
    cudaGetSymbolAddress((void**)&B1, g_B1);
    cudaGetSymbolAddress((void**)&B2, g_B2);
    cudaGetSymbolAddress((void**)&B3, g_B3);

    // loop smem: 2*ABUF + 2*BBUF; epilogue stage must also fit
    const int smem_g1 = 2 * 128 * 144 + 2 * 128 * 144;   // 73728  (stage 66048 fits)
    const int smem_g2 = 2 * 128 * 144 + 2 * 256 * 144;   // 110592 vs stage 131584 -> take max
    const int smem_g2f = 131584;
    const int smem_g3 = 2 * 128 * 144 + 2 * 64 * 144;    // 55296  (stage 33280 fits)
    cudaFuncSetAttribute(gemm_kernel<1>, cudaFuncAttributeMaxDynamicSharedMemorySize, smem_g1);
    cudaFuncSetAttribute(gemm_kernel<2>, cudaFuncAttributeMaxDynamicSharedMemorySize, smem_g2f);
    cudaFuncSetAttribute(gemm_kernel<3>, cudaFuncAttributeMaxDynamicSharedMemorySize, smem_g3);

    prep_w1<<<1, 128>>>(w1, B1);
    prep_w2<<<256, 256>>>(w2, B2);
    prep_w3<<<64, 256>>>(w3, B3);

    im2col1<<<256, 256>>>(x, A1);
    gemm_kernel<1><<<dim3(2048, 1), 256, smem_g1>>>(A1, B1, b1, g1, be1, m1, v1, h1);
    im2col2<<<dim3(256, 4), 256>>>(h1, A2);
    gemm_kernel<2><<<dim3(512, 1), 256, smem_g2f>>>(A2, B2, b2, g2, be2, m2, v2, h2);
    im2col3<<<dim3(256, 2), 256>>>(h2, A3);
    gemm_kernel<3><<<dim3(128, 1), 256, smem_g3>>>(A3, B3, b3, g3, be3, m3, v3, data);

    normalize_kernel<<<256, 256>>>(data);
    gram_kernel<<<dim3(16, 16), 256>>>(data, G);
    dist0_kernel<<<256, 256>>>(data, mu0, D0);
    kmeans_iter_kernel<<<1, 1024>>>(G, D0, (float*)d_out);
}

// round 10
// speedup vs baseline: 2.0627x; 1.1839x over previous
#include <cuda_runtime.h>
#include <cuda_fp16.h>
#include <math.h>
#include <stdint.h>

#define BN_EPS 1e-3f
#define SLOPE  0.1f
#define CT     30.0f

// ============================ scratch globals ============================
__device__ __half g_h1[256 * 128 * 1024];     // conv1 out fp16 NCHW
__device__ __half g_h2[256 * 256 * 256];      // conv2 out fp16 NCHW
__device__ float g_data[256 * 4096];
__device__ float g_G[256 * 256];
__device__ float g_D0[256 * 16];
__device__ __half g_A1[256 * 1024 * 64];      // im2col conv1 (K=64: w27|pad)
__device__ __half g_A2[65536ull * 1152];      // im2col conv2
__device__ __half g_A3[16384ull * 2304];      // im2col conv3
__device__ __half g_B1[128 * 64];
__device__ __half g_B2[256 * 1152];
__device__ __half g_B3[64 * 2304];

__device__ __forceinline__ uint32_t smem_u32(const void* p) {
    uint32_t a;
    asm("{ .reg .u64 t; cvta.to.shared.u64 t, %1; cvt.u32.u64 %0, t; }" : "=r"(a) : "l"(p));
    return a;
}
__device__ __forceinline__ void cp_async16(uint32_t dst, const void* src) {
    asm volatile("cp.async.cg.shared.global [%0], [%1], 16;" :: "r"(dst), "l"(src));
}
__device__ __forceinline__ void ldsm_x4(uint32_t* f, uint32_t addr) {
    asm volatile("ldmatrix.sync.aligned.m8n8.x4.shared.b16 {%0,%1,%2,%3}, [%4];"
                 : "=r"(f[0]), "=r"(f[1]), "=r"(f[2]), "=r"(f[3]) : "r"(addr));
}
__device__ __forceinline__ void mma_f16(float* d, const uint32_t* a, const uint32_t* b) {
    asm volatile(
        "mma.sync.aligned.m16n8k16.row.col.f32.f16.f16.f32 "
        "{%0,%1,%2,%3}, {%4,%5,%6,%7}, {%8,%9}, {%0,%1,%2,%3};"
        : "+f"(d[0]), "+f"(d[1]), "+f"(d[2]), "+f"(d[3])
        : "r"(a[0]), "r"(a[1]), "r"(a[2]), "r"(a[3]), "r"(b[0]), "r"(b[1]));
}

// ============================ weight prep (plain fp16) ============================
__global__ __launch_bounds__(128) void prep_w1(const float* __restrict__ w, __half* __restrict__ o)
{
    int oc = threadIdx.x;
    __half* row = o + oc * 64;
#pragma unroll
    for (int j = 0; j < 64; j++) row[j] = __ushort_as_half((unsigned short)0);
#pragma unroll
    for (int j = 0; j < 27; j++) row[j] = __float2half_rn(w[oc * 27 + j]);
}
__global__ __launch_bounds__(256) void prep_w2(const float* __restrict__ w, __half* __restrict__ o)
{
    int oc = blockIdx.x;
    for (int k = threadIdx.x; k < 1152; k += 256)
        o[oc * 1152 + k] = __float2half_rn(w[oc * 1152 + k]);
}
__global__ __launch_bounds__(256) void prep_w3(const float* __restrict__ w, __half* __restrict__ o)
{
    int oc = blockIdx.x;
    for (int k = threadIdx.x; k < 2304; k += 256)
        o[oc * 2304 + k] = __float2half_rn(w[oc * 2304 + k]);
}

// ============================ im2col ============================
__global__ __launch_bounds__(256) void im2col1(const float* __restrict__ x, __half* __restrict__ A)
{
    __shared__ float s[12288];
    int img = blockIdx.x, tid = threadIdx.x;
    const float* xin = x + img * 12288;
    for (int i = tid; i < 12288; i += 256) s[i] = xin[i];
    __syncthreads();
#pragma unroll
    for (int pp = 0; pp < 4; pp++) {
        int p = tid + pp * 256;
        int oh = p >> 5, ow = p & 31;
        uint32_t t[32];
#pragma unroll
        for (int i = 0; i < 32; i++) t[i] = 0;
#pragma unroll
        for (int j = 0; j < 27; j++) {
            int ic = j / 9, kk = j % 9, kh = kk / 3, kw = kk % 3;
            int ih = 2 * oh - 1 + kh, iw = 2 * ow - 1 + kw;
            float val = (ih >= 0 && ih < 64 && iw >= 0 && iw < 64) ? s[ic * 4096 + ih * 64 + iw] : 0.f;
            t[j >> 1] |= (uint32_t)__half_as_ushort(__float2half_rn(val)) << ((j & 1) * 16);
        }
        uint4* row = (uint4*)(A + ((size_t)(img * 1024 + p)) * 64);
#pragma unroll
        for (int w = 0; w < 8; w++) row[w] = make_uint4(t[4*w], t[4*w+1], t[4*w+2], t[4*w+3]);
    }
}

// grid(256, 4): fp16 input, pure bit-shuffle
__global__ __launch_bounds__(256) void im2col2(const __half* __restrict__ in, __half* __restrict__ A)
{
    __shared__ __half s[8192];
    int img = blockIdx.x, tid = threadIdx.x;
    int p = tid, oh = p >> 4, ow = p & 15;
    char* rowb = (char*)(A + ((size_t)(img * 256 + p)) * 1152);
    for (int ii = 0; ii < 4; ii++) {
        int icb = blockIdx.y * 4 + ii;
        __syncthreads();
        const uint4* ip4 = (const uint4*)(in + ((size_t)img * 128 + icb * 8) * 1024);
        uint4* s4 = (uint4*)s;
        for (int i = tid; i < 1024; i += 256) s4[i] = ip4[i];
        __syncthreads();
        uint32_t th[36];
#pragma unroll
        for (int u = 0; u < 36; u++) {
            uint32_t hv = 0;
#pragma unroll
            for (int half = 0; half < 2; half++) {
                int j = 2 * u + half;
                int ic8 = j / 9, kk = j % 9, kh = kk / 3, kw = kk % 3;
                int ih = 2 * oh - 1 + kh, iw = 2 * ow - 1 + kw;
                unsigned short hb = (ih >= 0 && ih < 32 && iw >= 0 && iw < 32)
                                        ? __half_as_ushort(s[ic8 * 1024 + (ih << 5) + iw]) : (unsigned short)0;
                hv |= (uint32_t)hb << (half * 16);
            }
            th[u] = hv;
        }
        uint4* oh4 = (uint4*)(rowb + icb * 144);
#pragma unroll
        for (int w = 0; w < 9; w++)
            oh4[w] = make_uint4(th[4*w], th[4*w+1], th[4*w+2], th[4*w+3]);
    }
}

// grid(256, 2): fp16 input
__global__ __launch_bounds__(256) void im2col3(const __half* __restrict__ in, __half* __restrict__ A)
{
    __shared__ __half s[8192];
    int img = blockIdx.x, tid = threadIdx.x;
    int p = tid & 63, q = tid >> 6;
    int oh = p >> 3, ow = p & 7;
    char* rowb = (char*)(A + ((size_t)(img * 64 + p)) * 2304);
    for (int ii = 0; ii < 4; ii++) {
        int icb = blockIdx.y * 4 + ii;
        __syncthreads();
        const uint4* ip4 = (const uint4*)(in + ((size_t)img * 256 + icb * 32) * 256);
        uint4* s4 = (uint4*)s;
        for (int i = tid; i < 1024; i += 256) s4[i] = ip4[i];
        __syncthreads();
        uint32_t th[36];
#pragma unroll
        for (int u = 0; u < 36; u++) {
            uint32_t hv = 0;
#pragma unroll
            for (int half = 0; half < 2; half++) {
                int j = 2 * u + half;
                int ic8 = j / 9, kk = j % 9, kh = kk / 3, kw = kk % 3;
                int ih = 2 * oh - 1 + kh, iw = 2 * ow - 1 + kw;
                unsigned short hb = (ih >= 0 && ih < 16 && iw >= 0 && iw < 16)
                                        ? __half_as_ushort(s[(q * 8 + ic8) * 256 + (ih << 4) + iw]) : (unsigned short)0;
                hv |= (uint32_t)hb << (half * 16);
            }
            th[u] = hv;
        }
        uint4* oh4 = (uint4*)(rowb + icb * 576 + q * 144);
#pragma unroll
        for (int w = 0; w < 9; w++)
            oh4[w] = make_uint4(th[4*w], th[4*w+1], th[4*w+2], th[4*w+3]);
    }
}

// ============================ HMMA GEMM (pure fp16) ============================
// CONV 1/2 write __half out; CONV 3 writes float embeds.
template<int CONV>
__global__ __launch_bounds__(256)
void gemm_kernel(const __half* __restrict__ A, const __half* __restrict__ Bw,
                 const float* __restrict__ bias, const float* __restrict__ g,
                 const float* __restrict__ beta, const float* __restrict__ m,
                 const float* __restrict__ v, void* __restrict__ out_v)
{
    constexpr int N  = (CONV == 2) ? 256 : ((CONV == 1) ? 128 : 64);
    constexpr int KS = (CONV == 1) ? 64 : ((CONV == 2) ? 1152 : 2304);
    constexpr int NC = KS / 64;
    constexpr int BN = N;
    constexpr int WN = BN / 2;
    constexpr int NT = WN / 8;
    constexpr int ABUF = 128 * 144;
    constexpr int BBUF = BN * 144;
    constexpr int BGI = (BN * 8) / 256;
    constexpr int P = BN + 1;

    extern __shared__ __align__(16) char smem[];
    __shared__ float scs[256], shs[256];

    int tid = threadIdx.x, wid = tid >> 5, lane = tid & 31;
    int wm = wid & 3, wn = wid >> 2;
    int rowbase = blockIdx.x * 128;

    if (tid < N) {
        float sc = g[tid] / sqrtf(v[tid] + BN_EPS);
        scs[tid] = sc;
        shs[tid] = beta[tid] - m[tid] * sc + bias[tid] * sc;
    }

    uint32_t sb = smem_u32(smem);

    float acc[2][NT][4];
#pragma unroll
    for (int i = 0; i < 2; i++)
#pragma unroll
        for (int j = 0; j < NT; j++)
#pragma unroll
            for (int q = 0; q < 4; q++) acc[i][j][q] = 0.f;

    auto issue_copy = [&](int c) {
        int buf = c & 1;
        uint32_t ab = sb + buf * (ABUF + BBUF);
        uint32_t bb = ab + ABUF;
#pragma unroll
        for (int i = 0; i < 4; i++) {
            int gi = tid + 256 * i; int rr = gi >> 3, gc = gi & 7;
            cp_async16(ab + rr * 144 + gc * 16,
                       (const char*)A + ((size_t)(rowbase + rr) * KS + c * 64) * 2 + gc * 16);
        }
#pragma unroll
        for (int i = 0; i < BGI; i++) {
            int gi = tid + 256 * i; int rr = gi >> 3, gc = gi & 7;
            cp_async16(bb + rr * 144 + gc * 16,
                       (const char*)Bw + ((size_t)rr * KS + c * 64) * 2 + gc * 16);
        }
        asm volatile("cp.async.commit_group;");
    };

    issue_copy(0);
    for (int c = 0; c < NC; c++) {
        if (c + 1 < NC) {
            issue_copy(c + 1);
            asm volatile("cp.async.wait_group 1;");
        } else {
            asm volatile("cp.async.wait_group 0;");
        }
        __syncthreads();

        int buf = c & 1;
        uint32_t ab = sb + buf * (ABUF + BBUF);
        uint32_t bb = ab + ABUF;
#pragma unroll
        for (int ks = 0; ks < 4; ks++) {
            uint32_t af[2][4];
#pragma unroll
            for (int mt = 0; mt < 2; mt++) {
                uint32_t addr = ab + (wm * 32 + mt * 16 + (lane & 15)) * 144
                                + ks * 32 + ((lane >> 4) << 4);
                ldsm_x4(af[mt], addr);
            }
#pragma unroll
            for (int nt2 = 0; nt2 < NT / 2; nt2++) {
                uint32_t bf[4];
                uint32_t addr = bb + (wn * WN + nt2 * 16 + (lane & 7) + (((lane >> 4) & 1) << 3)) * 144
                                + ks * 32 + (((lane >> 3) & 1) << 4);
                ldsm_x4(bf, addr);
#pragma unroll
                for (int mt = 0; mt < 2; mt++) {
                    mma_f16(acc[mt][2 * nt2],     af[mt], bf);
                    mma_f16(acc[mt][2 * nt2 + 1], af[mt], bf + 2);
                }
            }
        }
        __syncthreads();
    }

    float* stage = (float*)smem;
#pragma unroll
    for (int mt = 0; mt < 2; mt++)
#pragma unroll
        for (int nt = 0; nt < NT; nt++) {
            int r0 = wm * 32 + mt * 16 + (lane >> 2);
            int c0 = wn * WN + nt * 8 + 2 * (lane & 3);
            stage[r0 * P + c0]           = acc[mt][nt][0];
            stage[r0 * P + c0 + 1]       = acc[mt][nt][1];
            stage[(r0 + 8) * P + c0]     = acc[mt][nt][2];
            stage[(r0 + 8) * P + c0 + 1] = acc[mt][nt][3];
        }
    __syncthreads();

#pragma unroll
    for (int j = 0; j < BN / 8; j++) {
        int colL = wid * (BN / 8) + j;
        float sc = scs[colL], sh = shs[colL];
#pragma unroll
        for (int it = 0; it < 4; it++) {
            int r = it * 32 + lane;
            float y = stage[r * P + colL] * sc + sh;
            y = y > 0.f ? y : SLOPE * y;
            int grow = rowbase + r;
            if (CONV == 1) {
                int img = grow >> 10, p = grow & 1023;
                ((__half*)out_v)[((size_t)(img * 128 + colL)) * 1024 + p] = __float2half_rn(y);
            } else if (CONV == 2) {
                int img = grow >> 8, p = grow & 255;
                ((__half*)out_v)[((size_t)(img * 256 + colL)) * 256 + p] = __float2half_rn(y);
            } else {
                int img = grow >> 6, p = grow & 63;
                ((float*)out_v)[(size_t)img * 4096 + colL * 64 + p] = y;
            }
        }
    }
}

// ============================ k-means ============================
__global__ __launch_bounds__(256) void normalize_kernel(float* __restrict__ data)
{
    int row = blockIdx.x, tid = threadIdx.x;
    float* dr = data + row * 4096;
    float vals[16];
    float s = 0.f;
#pragma unroll
    for (int i = 0; i < 16; i++) { vals[i] = dr[tid + i * 256]; s = fmaf(vals[i], vals[i], s); }
    __shared__ float sm[9];
    int lane = tid & 31, warp = tid >> 5;
#pragma unroll
    for (int off = 16; off > 0; off >>= 1) s += __shfl_down_sync(0xffffffffu, s, off);
    if (lane == 0) sm[warp] = s;
    __syncthreads();
    if (tid == 0) {
        float t = 0.f;
        for (int w = 0; w < 8; w++) t += sm[w];
        sm[8] = 1.f / sqrtf(t);
    }
    __syncthreads();
    float inv = sm[8];
#pragma unroll
    for (int i = 0; i < 16; i++) dr[tid + i * 256] = vals[i] * inv;
}

__global__ __launch_bounds__(256) void gram_kernel(const float* __restrict__ data, float* __restrict__ G)
{
    __shared__ float at[16][129];
    __shared__ float bt[16][129];
    int tid = threadIdx.x;
    int ty = tid >> 4, tx = tid & 15;
    int r0 = blockIdx.y * 16, c0 = blockIdx.x * 16;
    float acc = 0.f;
    for (int kc = 0; kc < 4096; kc += 128) {
        __syncthreads();
        for (int i = tid; i < 2048; i += 256) {
            int rr = i >> 7, cc = i & 127;
            at[rr][cc] = data[(size_t)(r0 + rr) * 4096 + kc + cc];
            bt[rr][cc] = data[(size_t)(c0 + rr) * 4096 + kc + cc];
        }
        __syncthreads();
#pragma unroll 16
        for (int k = 0; k < 128; k++) acc = fmaf(at[ty][k], bt[tx][k], acc);
    }
    G[(r0 + ty) * 256 + c0 + tx] = acc;
}

__global__ __launch_bounds__(256) void dist0_kernel(
    const float* __restrict__ data, const float* __restrict__ mu, float* __restrict__ dout)
{
    int row = blockIdx.x, tid = threadIdx.x;
    const float* dr = data + row * 4096;
    float acc[16];
#pragma unroll
    for (int k = 0; k < 16; k++) acc[k] = 0.f;
#pragma unroll 4
    for (int i = 0; i < 16; i++) {
        int j = tid + i * 256;
        float dj = __ldg(dr + j);
#pragma unroll
        for (int k = 0; k < 16; k++) acc[k] = fmaf(dj, __ldg(mu + k * 4096 + j), acc[k]);
    }
    __shared__ float wsum[8][16];
    int lane = tid & 31, warp = tid >> 5;
#pragma unroll
    for (int k = 0; k < 16; k++) {
        float vv = acc[k];
#pragma unroll
        for (int off = 16; off > 0; off >>= 1) vv += __shfl_down_sync(0xffffffffu, vv, off);
        if (lane == 0) wsum[warp][k] = vv;
    }
    __syncthreads();
    if (tid < 16) {
        float s = 0.f;
#pragma unroll
        for (int w = 0; w < 8; w++) s += wsum[w][tid];
        dout[row * 16 + tid] = s;
    }
}

__global__ __launch_bounds__(1024) void kmeans_iter_kernel(
    const float* __restrict__ G, const float* __restrict__ D0, float* __restrict__ out)
{
    __shared__ float rD[256 * 16];
    __shared__ float part[32][16];
    __shared__ float invcs[16];
    int tid = threadIdx.x;
    int row = tid >> 2, kg = tid & 3;

    for (int it = 0; it < 12; it++) {
        float L[4];
        if (it == 0) {
#pragma unroll
            for (int i = 0; i < 4; i++) L[i] = CT * D0[row * 16 + kg * 4 + i];
        } else {
            float a0 = 0.f, a1 = 0.f, a2 = 0.f, a3 = 0.f;
            const float4* gr = (const float4*)(G + (size_t)row * 256);
            const float4* rp = (const float4*)&rD[kg * 4];
#pragma unroll 8
            for (int n4 = 0; n4 < 64; n4++) {
                float4 gv = __ldg(gr + n4);
                float4 r0 = rp[n4 * 16];
                float4 r1 = rp[n4 * 16 + 4];
                float4 r2 = rp[n4 * 16 + 8];
                float4 r3 = rp[n4 * 16 + 12];
                a0 += gv.x * r0.x + gv.y * r1.x + gv.z * r2.x + gv.w * r3.x;
                a1 += gv.x * r0.y + gv.y * r1.y + gv.z * r2.y + gv.w * r3.y;
                a2 += gv.x * r0.z + gv.y * r1.z + gv.z * r2.z + gv.w * r3.z;
                a3 += gv.x * r0.w + gv.y * r1.w + gv.z * r2.w + gv.w * r3.w;
            }
            L[0] = CT * a0; L[1] = CT * a1; L[2] = CT * a2; L[3] = CT * a3;
        }
        float mx = fmaxf(fmaxf(L[0], L[1]), fmaxf(L[2], L[3]));
        mx = fmaxf(mx, __shfl_xor_sync(0xffffffffu, mx, 1));
        mx = fmaxf(mx, __shfl_xor_sync(0xffffffffu, mx, 2));
        float e[4]; float s = 0.f;
#pragma unroll
        for (int i = 0; i < 4; i++) { e[i] = expf(L[i] - mx); s += e[i]; }
        s += __shfl_xor_sync(0xffffffffu, s, 1);
        s += __shfl_xor_sync(0xffffffffu, s, 2);
        float inv = 1.f / s;
#pragma unroll
        for (int i = 0; i < 4; i++) e[i] *= inv;

        if (it == 11) {
            *(float4*)&out[row * 16 + kg * 4] = make_float4(e[0], e[1], e[2], e[3]);
            return;
        }
        __syncthreads();
        *(float4*)&rD[row * 16 + kg * 4] = make_float4(e[0], e[1], e[2], e[3]);
        __syncthreads();
        if (tid < 512) {
            int k = tid & 15, grp = tid >> 4;
            float ss = 0.f;
#pragma unroll
            for (int n = 0; n < 8; n++) ss += rD[(grp * 8 + n) * 16 + k];
            part[grp][k] = ss;
        }
        __syncthreads();
        if (tid < 16) {
            float ss = 0.f;
#pragma unroll
            for (int gq = 0; gq < 32; gq++) ss += part[gq][tid];
            invcs[tid] = 1.f / ss;
        }
        __syncthreads();
#pragma unroll
        for (int i = 0; i < 4; i++)
            rD[row * 16 + kg * 4 + i] = e[i] * invcs[kg * 4 + i];
        __syncthreads();
    }
}

// ============================ host ============================
extern "C" void kernel_launch(void* const* d_in, const int* in_sizes, int n_in,
                              void* d_out, int out_size)
{
    const float* x   = (const float*)d_in[0];
    const float* w1  = (const float*)d_in[1];
    const float* b1  = (const float*)d_in[2];
    const float* g1  = (const float*)d_in[3];
    const float* be1 = (const float*)d_in[4];
    const float* m1  = (const float*)d_in[5];
    const float* v1  = (const float*)d_in[6];
    const float* w2  = (const float*)d_in[7];
    const float* b2  = (const float*)d_in[8];
    const float* g2  = (const float*)d_in[9];
    const float* be2 = (const float*)d_in[10];
    const float* m2  = (const float*)d_in[11];
    const float* v2  = (const float*)d_in[12];
    const float* w3  = (const float*)d_in[13];
    const float* b3  = (const float*)d_in[14];
    const float* g3  = (const float*)d_in[15];
    const float* be3 = (const float*)d_in[16];
    const float* m3  = (const float*)d_in[17];
    const float* v3  = (const float*)d_in[18];
    const float* mu0 = (const float*)d_in[19];

    float *data, *G, *D0;
    __half *h1, *h2, *A1, *A2, *A3, *B1, *B2, *B3;
    cudaGetSymbolAddress((void**)&h1, g_h1);
    cudaGetSymbolAddress((void**)&h2, g_h2);
    cudaGetSymbolAddress((void**)&data, g_data);
    cudaGetSymbolAddress((void**)&G, g_G);
    cudaGetSymbolAddress((void**)&D0, g_D0);
    cudaGetSymbolAddress((void**)&A1, g_A1);
    cudaGetSymbolAddress((void**)&A2, g_A2);
    cudaGetSymbolAddress((void**)&A3, g_A3);
    cudaGetSymbolAddress((void**)&B1, g_B1);
    cudaGetSymbolAddress((void**)&B2, g_B2);
    cudaGetSymbolAddress((void**)&B3, g_B3);

    const int smem_g1 = 2 * (128 * 144 + 128 * 144);   // 73728  (stage 66048 fits)
    const int smem_g2 = 131584;                        // max(110592 loop, 131584 stage)
    const int smem_g3 = 2 * (128 * 144 + 64 * 144);    // 55296  (stage 33280 fits)
    cudaFuncSetAttribute(gemm_kernel<1>, cudaFuncAttributeMaxDynamicSharedMemorySize, smem_g1);
    cudaFuncSetAttribute(gemm_kernel<2>, cudaFuncAttributeMaxDynamicSharedMemorySize, smem_g2);
    cudaFuncSetAttribute(gemm_kernel<3>, cudaFuncAttributeMaxDynamicSharedMemorySize, smem_g3);

    prep_w1<<<1, 128>>>(w1, B1);
    prep_w2<<<256, 256>>>(w2, B2);
    prep_w3<<<64, 256>>>(w3, B3);

    im2col1<<<256, 256>>>(x, A1);
    gemm_kernel<1><<<dim3(2048, 1), 256, smem_g1>>>(A1, B1, b1, g1, be1, m1, v1, h1);
    im2col2<<<dim3(256, 4), 256>>>(h1, A2);
    gemm_kernel<2><<<dim3(512, 1), 256, smem_g2>>>(A2, B2, b2, g2, be2, m2, v2, h2);
    im2col3<<<dim3(256, 2), 256>>>(h2, A3);
    gemm_kernel<3><<<dim3(128, 1), 256, smem_g3>>>(A3, B3, b3, g3, be3, m3, v3, data);

    normalize_kernel<<<256, 256>>>(data);
    gram_kernel<<<dim3(16, 16), 256>>>(data, G);
    dist0_kernel<<<256, 256>>>(data, mu0, D0);
    kmeans_iter_kernel<<<1, 1024>>>(G, D0, (float*)d_out);
}

// round 11
// speedup vs baseline: 2.5865x; 1.2540x over previous
#include <cuda_runtime.h>
#include <cuda_fp16.h>
#include <math.h>
#include <stdint.h>

#define BN_EPS 1e-3f
#define SLOPE  0.1f
#define CT     30.0f

// ============================ scratch globals ============================
__device__ __half g_h1[256 * 32 * 32 * 128];  // conv1 out NHWC fp16
__device__ __half g_h2[256 * 16 * 16 * 256];  // conv2 out NHWC fp16
__device__ float g_data[256 * 4096];
__device__ float g_G[256 * 256];
__device__ float g_D0[256 * 16];
__device__ __half g_A1[256 * 1024 * 64];      // im2col conv1 (cheap; kept)
__device__ __half g_B1[128 * 64];
__device__ __half g_B2[256 * 1152];           // k = kk*128 + ic
__device__ __half g_B3[64 * 2304];            // k = kk*256 + ic

__device__ __forceinline__ uint32_t smem_u32(const void* p) {
    uint32_t a;
    asm("{ .reg .u64 t; cvta.to.shared.u64 t, %1; cvt.u32.u64 %0, t; }" : "=r"(a) : "l"(p));
    return a;
}
__device__ __forceinline__ void cp_async16(uint32_t dst, const void* src) {
    asm volatile("cp.async.cg.shared.global [%0], [%1], 16;" :: "r"(dst), "l"(src));
}
// zero-fill variant: src-size 0 -> 16 bytes of zeros, no memory access
__device__ __forceinline__ void cp_async16z(uint32_t dst, const void* src, int szbytes) {
    asm volatile("cp.async.cg.shared.global [%0], [%1], 16, %2;"
                 :: "r"(dst), "l"(src), "r"(szbytes));
}
__device__ __forceinline__ void ldsm_x4(uint32_t* f, uint32_t addr) {
    asm volatile("ldmatrix.sync.aligned.m8n8.x4.shared.b16 {%0,%1,%2,%3}, [%4];"
                 : "=r"(f[0]), "=r"(f[1]), "=r"(f[2]), "=r"(f[3]) : "r"(addr));
}
__device__ __forceinline__ void mma_f16(float* d, const uint32_t* a, const uint32_t* b) {
    asm volatile(
        "mma.sync.aligned.m16n8k16.row.col.f32.f16.f16.f32 "
        "{%0,%1,%2,%3}, {%4,%5,%6,%7}, {%8,%9}, {%0,%1,%2,%3};"
        : "+f"(d[0]), "+f"(d[1]), "+f"(d[2]), "+f"(d[3])
        : "r"(a[0]), "r"(a[1]), "r"(a[2]), "r"(a[3]), "r"(b[0]), "r"(b[1]));
}

// ============================ weight prep ============================
__global__ __launch_bounds__(128) void prep_w1(const float* __restrict__ w, __half* __restrict__ o)
{
    int oc = threadIdx.x;
    __half* row = o + oc * 64;
#pragma unroll
    for (int j = 0; j < 64; j++) row[j] = __ushort_as_half((unsigned short)0);
#pragma unroll
    for (int j = 0; j < 27; j++) row[j] = __float2half_rn(w[oc * 27 + j]);
}
// B2[oc][kk*128 + ic] = w2[oc][ic*9 + kk]
__global__ __launch_bounds__(256) void prep_w2(const float* __restrict__ w, __half* __restrict__ o)
{
    int oc = blockIdx.x;
    for (int k = threadIdx.x; k < 1152; k += 256) {
        int kk = k >> 7, ic = k & 127;
        o[oc * 1152 + k] = __float2half_rn(w[oc * 1152 + ic * 9 + kk]);
    }
}
// B3[oc][kk*256 + ic] = w3[oc][ic*9 + kk]
__global__ __launch_bounds__(256) void prep_w3(const float* __restrict__ w, __half* __restrict__ o)
{
    int oc = blockIdx.x;
    for (int k = threadIdx.x; k < 2304; k += 256) {
        int kk = k >> 8, ic = k & 255;
        o[oc * 2304 + k] = __float2half_rn(w[oc * 2304 + ic * 9 + kk]);
    }
}

// ============================ im2col1 (kept; A1 is small) ============================
__global__ __launch_bounds__(256) void im2col1(const float* __restrict__ x, __half* __restrict__ A)
{
    __shared__ float s[12288];
    int img = blockIdx.x, tid = threadIdx.x;
    const float* xin = x + img * 12288;
    for (int i = tid; i < 12288; i += 256) s[i] = xin[i];
    __syncthreads();
#pragma unroll
    for (int pp = 0; pp < 4; pp++) {
        int p = tid + pp * 256;
        int oh = p >> 5, ow = p & 31;
        uint32_t t[32];
#pragma unroll
        for (int i = 0; i < 32; i++) t[i] = 0;
#pragma unroll
        for (int j = 0; j < 27; j++) {
            int ic = j / 9, kk = j % 9, kh = kk / 3, kw = kk % 3;
            int ih = 2 * oh - 1 + kh, iw = 2 * ow - 1 + kw;
            float val = (ih >= 0 && ih < 64 && iw >= 0 && iw < 64) ? s[ic * 4096 + ih * 64 + iw] : 0.f;
            t[j >> 1] |= (uint32_t)__half_as_ushort(__float2half_rn(val)) << ((j & 1) * 16);
        }
        uint4* row = (uint4*)(A + ((size_t)(img * 1024 + p)) * 64);
#pragma unroll
        for (int w = 0; w < 8; w++) row[w] = make_uint4(t[4*w], t[4*w+1], t[4*w+2], t[4*w+3]);
    }
}

// ============================ HMMA GEMM (fp16, fused im2col gather for CONV 2/3) ============================
// CONV 1: A = materialized A1 [row][64].
// CONV 2: A = h1 NHWC [256][32][32][128]; K = kk*128+ic, 18 chunks (kk 0..8, icg 0..1).
// CONV 3: A = h2 NHWC [256][16][16][256]; K = kk*256+ic, 36 chunks (kk 0..8, icg 0..3).
// Output: CONV1 -> h1 NHWC (= GEMM row-major), CONV2 -> h2 NHWC, CONV3 -> float embeds.
template<int CONV>
__global__ __launch_bounds__(256)
void gemm_kernel(const __half* __restrict__ A, const __half* __restrict__ Bw,
                 const float* __restrict__ bias, const float* __restrict__ g,
                 const float* __restrict__ beta, const float* __restrict__ m,
                 const float* __restrict__ v, void* __restrict__ out_v)
{
    constexpr int N  = (CONV == 2) ? 256 : ((CONV == 1) ? 128 : 64);
    constexpr int KS = (CONV == 1) ? 64 : ((CONV == 2) ? 1152 : 2304);
    constexpr int NC = KS / 64;
    constexpr int BN = N;
    constexpr int WN = BN / 2;
    constexpr int NT = WN / 8;
    constexpr int ABUF = 128 * 144;
    constexpr int BBUF = BN * 144;
    constexpr int BGI = (BN * 8) / 256;
    constexpr int P = BN + 1;

    extern __shared__ __align__(16) char smem[];
    __shared__ float scs[256], shs[256];

    int tid = threadIdx.x, wid = tid >> 5, lane = tid & 31;
    int wm = wid & 3, wn = wid >> 2;
    int rowbase = blockIdx.x * 128;
    // conv2: one image-half per block
    int img0 = rowbase >> 8, p0 = rowbase & 255;

    if (tid < N) {
        float sc = g[tid] / sqrtf(v[tid] + BN_EPS);
        scs[tid] = sc;
        shs[tid] = beta[tid] - m[tid] * sc + bias[tid] * sc;
    }

    uint32_t sb = smem_u32(smem);

    float acc[2][NT][4];
#pragma unroll
    for (int i = 0; i < 2; i++)
#pragma unroll
        for (int j = 0; j < NT; j++)
#pragma unroll
            for (int q = 0; q < 4; q++) acc[i][j][q] = 0.f;

    auto issue_copy = [&](int c) {
        int buf = c & 1;
        uint32_t ab = sb + buf * (ABUF + BBUF);
        uint32_t bb = ab + ABUF;
        if (CONV == 1) {
#pragma unroll
            for (int i = 0; i < 4; i++) {
                int gi = tid + 256 * i; int rr = gi >> 3, gc = gi & 7;
                cp_async16(ab + rr * 144 + gc * 16,
                           (const char*)A + ((size_t)(rowbase + rr) * KS + c * 64) * 2 + gc * 16);
            }
        } else if (CONV == 2) {
            int kk = c >> 1, icg = c & 1;
            int kh = kk / 3, kw = kk - 3 * kh;
#pragma unroll
            for (int i = 0; i < 4; i++) {
                int gi = tid + 256 * i; int rr = gi >> 3, gc = gi & 7;
                int p = p0 + rr;
                int oh = p >> 4, ow = p & 15;
                int ih = 2 * oh - 1 + kh, iw = 2 * ow - 1 + kw;
                bool ok = ((unsigned)ih < 32u) && ((unsigned)iw < 32u);
                size_t off = (((size_t)img0 * 32 + (ok ? ih : 0)) * 32 + (ok ? iw : 0)) * 128
                             + icg * 64 + gc * 8;
                cp_async16z(ab + rr * 144 + gc * 16, (const char*)A + off * 2, ok ? 16 : 0);
            }
        } else {
            int kk = c >> 2, icg = c & 3;
            int kh = kk / 3, kw = kk - 3 * kh;
#pragma unroll
            for (int i = 0; i < 4; i++) {
                int gi = tid + 256 * i; int rr = gi >> 3, gc = gi & 7;
                int grow = rowbase + rr;
                int img = grow >> 6, p = grow & 63;
                int oh = p >> 3, ow = p & 7;
                int ih = 2 * oh - 1 + kh, iw = 2 * ow - 1 + kw;
                bool ok = ((unsigned)ih < 16u) && ((unsigned)iw < 16u);
                size_t off = (((size_t)img * 16 + (ok ? ih : 0)) * 16 + (ok ? iw : 0)) * 256
                             + icg * 64 + gc * 8;
                cp_async16z(ab + rr * 144 + gc * 16, (const char*)A + off * 2, ok ? 16 : 0);
            }
        }
#pragma unroll
        for (int i = 0; i < BGI; i++) {
            int gi = tid + 256 * i; int rr = gi >> 3, gc = gi & 7;
            cp_async16(bb + rr * 144 + gc * 16,
                       (const char*)Bw + ((size_t)rr * KS + c * 64) * 2 + gc * 16);
        }
        asm volatile("cp.async.commit_group;");
    };

    issue_copy(0);
    for (int c = 0; c < NC; c++) {
        if (c + 1 < NC) {
            issue_copy(c + 1);
            asm volatile("cp.async.wait_group 1;");
        } else {
            asm volatile("cp.async.wait_group 0;");
        }
        __syncthreads();

        int buf = c & 1;
        uint32_t ab = sb + buf * (ABUF + BBUF);
        uint32_t bb = ab + ABUF;
#pragma unroll
        for (int ks = 0; ks < 4; ks++) {
            uint32_t af[2][4];
#pragma unroll
            for (int mt = 0; mt < 2; mt++) {
                uint32_t addr = ab + (wm * 32 + mt * 16 + (lane & 15)) * 144
                                + ks * 32 + ((lane >> 4) << 4);
                ldsm_x4(af[mt], addr);
            }
#pragma unroll
            for (int nt2 = 0; nt2 < NT / 2; nt2++) {
                uint32_t bf[4];
                uint32_t addr = bb + (wn * WN + nt2 * 16 + (lane & 7) + (((lane >> 4) & 1) << 3)) * 144
                                + ks * 32 + (((lane >> 3) & 1) << 4);
                ldsm_x4(bf, addr);
#pragma unroll
                for (int mt = 0; mt < 2; mt++) {
                    mma_f16(acc[mt][2 * nt2],     af[mt], bf);
                    mma_f16(acc[mt][2 * nt2 + 1], af[mt], bf + 2);
                }
            }
        }
        __syncthreads();
    }

    float* stage = (float*)smem;
#pragma unroll
    for (int mt = 0; mt < 2; mt++)
#pragma unroll
        for (int nt = 0; nt < NT; nt++) {
            int r0 = wm * 32 + mt * 16 + (lane >> 2);
            int c0 = wn * WN + nt * 8 + 2 * (lane & 3);
            stage[r0 * P + c0]           = acc[mt][nt][0];
            stage[r0 * P + c0 + 1]       = acc[mt][nt][1];
            stage[(r0 + 8) * P + c0]     = acc[mt][nt][2];
            stage[(r0 + 8) * P + c0 + 1] = acc[mt][nt][3];
        }
    __syncthreads();

    if (CONV == 3) {
        // float embeds, layout img*4096 + col*64 + p (coalesced along p)
#pragma unroll
        for (int j = 0; j < BN / 8; j++) {
            int colL = wid * (BN / 8) + j;
            float sc = scs[colL], sh = shs[colL];
#pragma unroll
            for (int it = 0; it < 4; it++) {
                int r = it * 32 + lane;
                float y = stage[r * P + colL] * sc + sh;
                y = y > 0.f ? y : SLOPE * y;
                int grow = rowbase + r;
                int img = grow >> 6, p = grow & 63;
                ((float*)out_v)[(size_t)img * 4096 + colL * 64 + p] = y;
            }
        }
    } else {
        // NHWC half output = row-major GEMM matrix; fully coalesced half2 stores
        __half2* o2 = (__half2*)out_v;
#pragma unroll
        for (int rblk = 0; rblk < 16; rblk++) {
            int r = wid * 16 + rblk;
            size_t base2 = ((size_t)(rowbase + r) * BN) >> 1;
#pragma unroll
            for (int cc = lane; cc < BN / 2; cc += 32) {
                float y0 = stage[r * P + 2 * cc] * scs[2 * cc] + shs[2 * cc];
                float y1 = stage[r * P + 2 * cc + 1] * scs[2 * cc + 1] + shs[2 * cc + 1];
                y0 = y0 > 0.f ? y0 : SLOPE * y0;
                y1 = y1 > 0.f ? y1 : SLOPE * y1;
                o2[base2 + cc] = __floats2half2_rn(y0, y1);
            }
        }
    }
}

// ============================ k-means ============================
__global__ __launch_bounds__(256) void normalize_kernel(float* __restrict__ data)
{
    int row = blockIdx.x, tid = threadIdx.x;
    float* dr = data + row * 4096;
    float vals[16];
    float s = 0.f;
#pragma unroll
    for (int i = 0; i < 16; i++) { vals[i] = dr[tid + i * 256]; s = fmaf(vals[i], vals[i], s); }
    __shared__ float sm[9];
    int lane = tid & 31, warp = tid >> 5;
#pragma unroll
    for (int off = 16; off > 0; off >>= 1) s += __shfl_down_sync(0xffffffffu, s, off);
    if (lane == 0) sm[warp] = s;
    __syncthreads();
    if (tid == 0) {
        float t = 0.f;
        for (int w = 0; w < 8; w++) t += sm[w];
        sm[8] = 1.f / sqrtf(t);
    }
    __syncthreads();
    float inv = sm[8];
#pragma unroll
    for (int i = 0; i < 16; i++) dr[tid + i * 256] = vals[i] * inv;
}

__global__ __launch_bounds__(256) void gram_kernel(const float* __restrict__ data, float* __restrict__ G)
{
    __shared__ float at[16][129];
    __shared__ float bt[16][129];
    int tid = threadIdx.x;
    int ty = tid >> 4, tx = tid & 15;
    int r0 = blockIdx.y * 16, c0 = blockIdx.x * 16;
    float acc = 0.f;
    for (int kc = 0; kc < 4096; kc += 128) {
        __syncthreads();
        for (int i = tid; i < 2048; i += 256) {
            int rr = i >> 7, cc = i & 127;
            at[rr][cc] = data[(size_t)(r0 + rr) * 4096 + kc + cc];
            bt[rr][cc] = data[(size_t)(c0 + rr) * 4096 + kc + cc];
        }
        __syncthreads();
#pragma unroll 16
        for (int k = 0; k < 128; k++) acc = fmaf(at[ty][k], bt[tx][k], acc);
    }
    G[(r0 + ty) * 256 + c0 + tx] = acc;
}

__global__ __launch_bounds__(256) void dist0_kernel(
    const float* __restrict__ data, const float* __restrict__ mu, float* __restrict__ dout)
{
    int row = blockIdx.x, tid = threadIdx.x;
    const float* dr = data + row * 4096;
    float acc[16];
#pragma unroll
    for (int k = 0; k < 16; k++) acc[k] = 0.f;
#pragma unroll 4
    for (int i = 0; i < 16; i++) {
        int j = tid + i * 256;
        float dj = __ldg(dr + j);
#pragma unroll
        for (int k = 0; k < 16; k++) acc[k] = fmaf(dj, __ldg(mu + k * 4096 + j), acc[k]);
    }
    __shared__ float wsum[8][16];
    int lane = tid & 31, warp = tid >> 5;
#pragma unroll
    for (int k = 0; k < 16; k++) {
        float vv = acc[k];
#pragma unroll
        for (int off = 16; off > 0; off >>= 1) vv += __shfl_down_sync(0xffffffffu, vv, off);
        if (lane == 0) wsum[warp][k] = vv;
    }
    __syncthreads();
    if (tid < 16) {
        float s = 0.f;
#pragma unroll
        for (int w = 0; w < 8; w++) s += wsum[w][tid];
        dout[row * 16 + tid] = s;
    }
}

__global__ __launch_bounds__(1024) void kmeans_iter_kernel(
    const float* __restrict__ G, const float* __restrict__ D0, float* __restrict__ out)
{
    __shared__ float rD[256 * 16];
    __shared__ float part[32][16];
    __shared__ float invcs[16];
    int tid = threadIdx.x;
    int row = tid >> 2, kg = tid & 3;

    for (int it = 0; it < 12; it++) {
        float L[4];
        if (it == 0) {
#pragma unroll
            for (int i = 0; i < 4; i++) L[i] = CT * D0[row * 16 + kg * 4 + i];
        } else {
            float a0 = 0.f, a1 = 0.f, a2 = 0.f, a3 = 0.f;
            const float4* gr = (const float4*)(G + (size_t)row * 256);
            const float4* rp = (const float4*)&rD[kg * 4];
#pragma unroll 8
            for (int n4 = 0; n4 < 64; n4++) {
                float4 gv = __ldg(gr + n4);
                float4 r0 = rp[n4 * 16];
                float4 r1 = rp[n4 * 16 + 4];
                float4 r2 = rp[n4 * 16 + 8];
                float4 r3 = rp[n4 * 16 + 12];
                a0 += gv.x * r0.x + gv.y * r1.x + gv.z * r2.x + gv.w * r3.x;
                a1 += gv.x * r0.y + gv.y * r1.y + gv.z * r2.y + gv.w * r3.y;
                a2 += gv.x * r0.z + gv.y * r1.z + gv.z * r2.z + gv.w * r3.z;
                a3 += gv.x * r0.w + gv.y * r1.w + gv.z * r2.w + gv.w * r3.w;
            }
            L[0] = CT * a0; L[1] = CT * a1; L[2] = CT * a2; L[3] = CT * a3;
        }
        float mx = fmaxf(fmaxf(L[0], L[1]), fmaxf(L[2], L[3]));
        mx = fmaxf(mx, __shfl_xor_sync(0xffffffffu, mx, 1));
        mx = fmaxf(mx, __shfl_xor_sync(0xffffffffu, mx, 2));
        float e[4]; float s = 0.f;
#pragma unroll
        for (int i = 0; i < 4; i++) { e[i] = expf(L[i] - mx); s += e[i]; }
        s += __shfl_xor_sync(0xffffffffu, s, 1);
        s += __shfl_xor_sync(0xffffffffu, s, 2);
        float inv = 1.f / s;
#pragma unroll
        for (int i = 0; i < 4; i++) e[i] *= inv;

        if (it == 11) {
            *(float4*)&out[row * 16 + kg * 4] = make_float4(e[0], e[1], e[2], e[3]);
            return;
        }
        __syncthreads();
        *(float4*)&rD[row * 16 + kg * 4] = make_float4(e[0], e[1], e[2], e[3]);
        __syncthreads();
        if (tid < 512) {
            int k = tid & 15, grp = tid >> 4;
            float ss = 0.f;
#pragma unroll
            for (int n = 0; n < 8; n++) ss += rD[(grp * 8 + n) * 16 + k];
            part[grp][k] = ss;
        }
        __syncthreads();
        if (tid < 16) {
            float ss = 0.f;
#pragma unroll
            for (int gq = 0; gq < 32; gq++) ss += part[gq][tid];
            invcs[tid] = 1.f / ss;
        }
        __syncthreads();
#pragma unroll
        for (int i = 0; i < 4; i++)
            rD[row * 16 + kg * 4 + i] = e[i] * invcs[kg * 4 + i];
        __syncthreads();
    }
}

// ============================ host ============================
extern "C" void kernel_launch(void* const* d_in, const int* in_sizes, int n_in,
                              void* d_out, int out_size)
{
    const float* x   = (const float*)d_in[0];
    const float* w1  = (const float*)d_in[1];
    const float* b1  = (const float*)d_in[2];
    const float* g1  = (const float*)d_in[3];
    const float* be1 = (const float*)d_in[4];
    const float* m1  = (const float*)d_in[5];
    const float* v1  = (const float*)d_in[6];
    const float* w2  = (const float*)d_in[7];
    const float* b2  = (const float*)d_in[8];
    const float* g2  = (const float*)d_in[9];
    const float* be2 = (const float*)d_in[10];
    const float* m2  = (const float*)d_in[11];
    const float* v2  = (const float*)d_in[12];
    const float* w3  = (const float*)d_in[13];
    const float* b3  = (const float*)d_in[14];
    const float* g3  = (const float*)d_in[15];
    const float* be3 = (const float*)d_in[16];
    const float* m3  = (const float*)d_in[17];
    const float* v3  = (const float*)d_in[18];
    const float* mu0 = (const float*)d_in[19];

    float *data, *G, *D0;
    __half *h1, *h2, *A1, *B1, *B2, *B3;
    cudaGetSymbolAddress((void**)&h1, g_h1);
    cudaGetSymbolAddress((void**)&h2, g_h2);
    cudaGetSymbolAddress((void**)&data, g_data);
    cudaGetSymbolAddress((void**)&G, g_G);
    cudaGetSymbolAddress((void**)&D0, g_D0);
    cudaGetSymbolAddress((void**)&A1, g_A1);
    cudaGetSymbolAddress((void**)&B1, g_B1);
    cudaGetSymbolAddress((void**)&B2, g_B2);
    cudaGetSymbolAddress((void**)&B3, g_B3);

    const int smem_g1 = 2 * (128 * 144 + 128 * 144);   // 73728 (stage 66048 fits)
    const int smem_g2 = 131584;                        // max(loop 110592, stage 131584)
    const int smem_g3 = 2 * (128 * 144 + 64 * 144);    // 55296 (stage 33280 fits)
    cudaFuncSetAttribute(gemm_kernel<1>, cudaFuncAttributeMaxDynamicSharedMemorySize, smem_g1);
    cudaFuncSetAttribute(gemm_kernel<2>, cudaFuncAttributeMaxDynamicSharedMemorySize, smem_g2);
    cudaFuncSetAttribute(gemm_kernel<3>, cudaFuncAttributeMaxDynamicSharedMemorySize, smem_g3);

    prep_w1<<<1, 128>>>(w1, B1);
    prep_w2<<<256, 256>>>(w2, B2);
    prep_w3<<<64, 256>>>(w3, B3);

    im2col1<<<256, 256>>>(x, A1);
    gemm_kernel<1><<<dim3(2048, 1), 256, smem_g1>>>(A1, B1, b1, g1, be1, m1, v1, h1);
    gemm_kernel<2><<<dim3(512, 1), 256, smem_g2>>>(h1, B2, b2, g2, be2, m2, v2, h2);
    gemm_kernel<3><<<dim3(128, 1), 256, smem_g3>>>(h2, B3, b3, g3, be3, m3, v3, data);

    normalize_kernel<<<256, 256>>>(data);
    gram_kernel<<<dim3(16, 16), 256>>>(data, G);
    dist0_kernel<<<256, 256>>>(data, mu0, D0);
    kmeans_iter_kernel<<<1, 1024>>>(G, D0, (float*)d_out);
}